// round 1
// baseline (speedup 1.0000x reference)
#include <cuda_runtime.h>
#include <cstddef>

#define Nn 50000
#define Ee 800000
#define D 128
#define NODE_IN 19
#define EDGE_IN 4
#define STEPS 5
#define EPSf 1e-5f

// ---------------- device scratch (no allocations allowed) ----------------
__device__ float g_hn[Nn * D];    // node state
__device__ float g_acc[Nn * D];   // scatter accumulator / conv agg
__device__ float g_h[Nn * D];     // h = x @ W
__device__ float g_y[Nn * D];     // post conv1 (leaky) activations
__device__ float g_cnt[Nn];       // src edge counts (scatter-mean denom)
__device__ float g_dis[Nn];       // deg accumulation then deg^{-1/2}
__device__ float g_bnsum[D];
__device__ float g_bnsq[D];
__device__ float g_bnscale[D];
__device__ float g_bnshift[D];

__device__ __forceinline__ float leaky(float v) { return v > 0.f ? v : 0.05f * v; }

// vector reduction add (sm_90+): 4 floats in one red op
__device__ __forceinline__ void red4(float* p, float a, float b, float c, float d) {
    asm volatile("red.global.add.v4.f32 [%0], {%1,%2,%3,%4};"
                 :: "l"(p), "f"(a), "f"(b), "f"(c), "f"(d) : "memory");
}

// ---------------- small utility kernels ----------------
__global__ void k_zero() {
    int i = blockIdx.x * blockDim.x + threadIdx.x;
    int stride = gridDim.x * blockDim.x;
    for (int j = i; j < Nn * D; j += stride) g_acc[j] = 0.f;
    for (int j = i; j < Nn; j += stride) { g_cnt[j] = 0.f; g_dis[j] = 0.f; }
}

__global__ void k_count(const int* __restrict__ ei) {
    int e = blockIdx.x * blockDim.x + threadIdx.x;
    if (e >= Ee) return;
    atomicAdd(&g_cnt[ei[e]], 1.f);        // src counts
    atomicAdd(&g_dis[ei[Ee + e]], 1.f);   // dst degree
}

__global__ void k_dis() {
    int i = blockIdx.x * blockDim.x + threadIdx.x;
    if (i < Nn) g_dis[i] = rsqrtf(g_dis[i] + 1.0f);
}

__global__ void k_mix() {
    int i = blockIdx.x * blockDim.x + threadIdx.x;
    if (i < Nn * D) g_hn[i] += g_acc[i] / fmaxf(g_cnt[i >> 7], 1.f);
}

__global__ void k_bnzero() {
    int c = threadIdx.x;
    if (c < D) { g_bnsum[c] = 0.f; g_bnsq[c] = 0.f; }
}

__global__ void k_post1(const float* __restrict__ bias) {
    int c = threadIdx.x;   // 128 threads
    float b = bias[c];
    float s = 0.f, q = 0.f;
    for (int row = blockIdx.x; row < Nn; row += gridDim.x) {
        float v = g_acc[(size_t)row * D + c] + b;
        v = leaky(v);
        g_y[(size_t)row * D + c] = v;
        s += v; q += v * v;
    }
    atomicAdd(&g_bnsum[c], s);
    atomicAdd(&g_bnsq[c], q);
}

__global__ void k_bnfin(const float* __restrict__ g, const float* __restrict__ b) {
    int c = threadIdx.x;
    if (c < D) {
        float m = g_bnsum[c] * (1.f / (float)Nn);
        float v = g_bnsq[c] * (1.f / (float)Nn) - m * m;
        float sc = g[c] * rsqrtf(v + EPSf);
        g_bnscale[c] = sc;
        g_bnshift[c] = b[c] - m * sc;
    }
}

__global__ void k_resid(const float* __restrict__ bias) {
    int i = blockIdx.x * blockDim.x + threadIdx.x;
    if (i < Nn * D) g_hn[i] += g_acc[i] + bias[i & (D - 1)];
}

// ---------------- fused MLP3 + LayerNorm ----------------
// MODE 0: write to out (node encoder -> g_hn)
// MODE 1: red.v4 scatter to g_acc[esrc[row]] (edge encoder)
// MODE 2: write to out (decoder -> d_out)
template <int KIN, int MODE>
__global__ void __launch_bounds__(256) k_mlp(
    const float* __restrict__ in, const int* __restrict__ esrc,
    const float* __restrict__ W1, const float* __restrict__ b1,
    const float* __restrict__ W2, const float* __restrict__ b2,
    const float* __restrict__ W3, const float* __restrict__ b3,
    const float* __restrict__ lng, const float* __restrict__ lnb,
    float* __restrict__ out, int M)
{
    extern __shared__ float sh[];
    float* W1s = sh;
    float* W2s = W1s + KIN * D;
    float* W3s = W2s + D * D;
    float* cst = W3s + D * D;                 // b1,b2,b3,g,b : 5*D
    float* inb = cst + 5 * D;
    constexpr int INB = (KIN == D) ? 0 : 32 * KIN;
    float* rb = inb + INB;                    // 8 warps * 4 rows * D

    int tid = threadIdx.x, lane = tid & 31, wid = tid >> 5;
    for (int i = tid; i < KIN * D / 4; i += 256)
        ((float4*)W1s)[i] = ((const float4*)W1)[i];
    for (int i = tid; i < D * D / 4; i += 256) {
        ((float4*)W2s)[i] = ((const float4*)W2)[i];
        ((float4*)W3s)[i] = ((const float4*)W3)[i];
    }
    if (tid < D) {
        cst[tid] = b1[tid]; cst[D + tid] = b2[tid]; cst[2 * D + tid] = b3[tid];
        cst[3 * D + tid] = lng[tid]; cst[4 * D + tid] = lnb[tid];
    }
    __syncthreads();

    int rowbase = (blockIdx.x * 8 + wid) * 4;
    float* myrb = rb + wid * (4 * D);
    float* myin = (KIN == D) ? myrb : (inb + wid * (4 * KIN));

    // load 4 input rows (clamped; tail rows recomputed, stores guarded)
    #pragma unroll
    for (int r = 0; r < 4; r++) {
        int row = min(rowbase + r, M - 1);
        for (int k = lane; k < KIN; k += 32)
            myin[r * KIN + k] = in[(size_t)row * KIN + k];
    }
    __syncwarp();

    int c0 = lane * 4;
    float a[4][4];

    // ---- layer 1 ----
    #pragma unroll
    for (int r = 0; r < 4; r++)
        #pragma unroll
        for (int j = 0; j < 4; j++) a[r][j] = cst[c0 + j];
    for (int k = 0; k < KIN; k++) {
        float4 w = *(float4*)&W1s[k * D + c0];
        #pragma unroll
        for (int r = 0; r < 4; r++) {
            float x = myin[r * KIN + k];
            a[r][0] = fmaf(x, w.x, a[r][0]); a[r][1] = fmaf(x, w.y, a[r][1]);
            a[r][2] = fmaf(x, w.z, a[r][2]); a[r][3] = fmaf(x, w.w, a[r][3]);
        }
    }
    __syncwarp();
    #pragma unroll
    for (int r = 0; r < 4; r++)
        #pragma unroll
        for (int j = 0; j < 4; j++) myrb[r * D + c0 + j] = leaky(a[r][j]);
    __syncwarp();

    // ---- layer 2 ----
    #pragma unroll
    for (int r = 0; r < 4; r++)
        #pragma unroll
        for (int j = 0; j < 4; j++) a[r][j] = cst[D + c0 + j];
    #pragma unroll 2
    for (int k = 0; k < D; k++) {
        float4 w = *(float4*)&W2s[k * D + c0];
        #pragma unroll
        for (int r = 0; r < 4; r++) {
            float x = myrb[r * D + k];
            a[r][0] = fmaf(x, w.x, a[r][0]); a[r][1] = fmaf(x, w.y, a[r][1]);
            a[r][2] = fmaf(x, w.z, a[r][2]); a[r][3] = fmaf(x, w.w, a[r][3]);
        }
    }
    __syncwarp();
    #pragma unroll
    for (int r = 0; r < 4; r++)
        #pragma unroll
        for (int j = 0; j < 4; j++) myrb[r * D + c0 + j] = leaky(a[r][j]);
    __syncwarp();

    // ---- layer 3 ----
    #pragma unroll
    for (int r = 0; r < 4; r++)
        #pragma unroll
        for (int j = 0; j < 4; j++) a[r][j] = cst[2 * D + c0 + j];
    #pragma unroll 2
    for (int k = 0; k < D; k++) {
        float4 w = *(float4*)&W3s[k * D + c0];
        #pragma unroll
        for (int r = 0; r < 4; r++) {
            float x = myrb[r * D + k];
            a[r][0] = fmaf(x, w.x, a[r][0]); a[r][1] = fmaf(x, w.y, a[r][1]);
            a[r][2] = fmaf(x, w.z, a[r][2]); a[r][3] = fmaf(x, w.w, a[r][3]);
        }
    }

    // ---- LayerNorm + emit ----
    #pragma unroll
    for (int r = 0; r < 4; r++) {
        float s = a[r][0] + a[r][1] + a[r][2] + a[r][3];
        float q = a[r][0]*a[r][0] + a[r][1]*a[r][1] + a[r][2]*a[r][2] + a[r][3]*a[r][3];
        #pragma unroll
        for (int off = 16; off > 0; off >>= 1) {
            s += __shfl_xor_sync(0xffffffffu, s, off);
            q += __shfl_xor_sync(0xffffffffu, q, off);
        }
        float m = s * (1.0f / (float)D);
        float var = q * (1.0f / (float)D) - m * m;
        float inv = rsqrtf(var + EPSf);
        int row = rowbase + r;
        if (row < M) {
            float o0 = (a[r][0] - m) * inv * cst[3 * D + c0 + 0] + cst[4 * D + c0 + 0];
            float o1 = (a[r][1] - m) * inv * cst[3 * D + c0 + 1] + cst[4 * D + c0 + 1];
            float o2 = (a[r][2] - m) * inv * cst[3 * D + c0 + 2] + cst[4 * D + c0 + 2];
            float o3 = (a[r][3] - m) * inv * cst[3 * D + c0 + 3] + cst[4 * D + c0 + 3];
            if (MODE == 1) {
                int sidx = esrc[row];
                red4(&g_acc[(size_t)sidx * D + c0], o0, o1, o2, o3);
            } else {
                float4 v4 = make_float4(o0, o1, o2, o3);
                *(float4*)&out[(size_t)row * D + c0] = v4;
            }
        }
    }
}

// ---------------- conv GEMM: h = f(x) @ W ; acc = h * dis^2 ----------------
__global__ void __launch_bounds__(256) k_gemm_conv(
    const float* __restrict__ x, const float* __restrict__ W, int use_bn)
{
    extern __shared__ float sh[];
    float* Ws = sh;               // D*D
    float* rb = sh + D * D;       // 8 warps * 8 rows * D
    int tid = threadIdx.x, lane = tid & 31, wid = tid >> 5;
    int c0 = lane * 4;

    for (int i = tid; i < D * D / 4; i += 256)
        ((float4*)Ws)[i] = ((const float4*)W)[i];

    float sc[4], sf[4];
    if (use_bn) {
        #pragma unroll
        for (int j = 0; j < 4; j++) { sc[j] = g_bnscale[c0 + j]; sf[j] = g_bnshift[c0 + j]; }
    }
    __syncthreads();

    int rowbase = (blockIdx.x * 8 + wid) * 8;
    float* myrb = rb + wid * (8 * D);
    #pragma unroll
    for (int r = 0; r < 8; r++) {
        int row = min(rowbase + r, Nn - 1);
        float4 v = *(const float4*)&x[(size_t)row * D + c0];
        if (use_bn) {
            v.x = fmaf(v.x, sc[0], sf[0]); v.y = fmaf(v.y, sc[1], sf[1]);
            v.z = fmaf(v.z, sc[2], sf[2]); v.w = fmaf(v.w, sc[3], sf[3]);
        }
        *(float4*)&myrb[r * D + c0] = v;
    }
    __syncwarp();

    float a[8][4];
    #pragma unroll
    for (int r = 0; r < 8; r++)
        #pragma unroll
        for (int j = 0; j < 4; j++) a[r][j] = 0.f;

    #pragma unroll 2
    for (int k = 0; k < D; k++) {
        float4 w = *(float4*)&Ws[k * D + c0];
        #pragma unroll
        for (int r = 0; r < 8; r++) {
            float xv = myrb[r * D + k];
            a[r][0] = fmaf(xv, w.x, a[r][0]); a[r][1] = fmaf(xv, w.y, a[r][1]);
            a[r][2] = fmaf(xv, w.z, a[r][2]); a[r][3] = fmaf(xv, w.w, a[r][3]);
        }
    }

    #pragma unroll
    for (int r = 0; r < 8; r++) {
        int row = rowbase + r;
        if (row < Nn) {
            float dd = g_dis[row];
            float d2 = dd * dd;
            float4 h4 = make_float4(a[r][0], a[r][1], a[r][2], a[r][3]);
            *(float4*)&g_h[(size_t)row * D + c0] = h4;
            float4 a4 = make_float4(h4.x * d2, h4.y * d2, h4.z * d2, h4.w * d2);
            *(float4*)&g_acc[(size_t)row * D + c0] = a4;
        }
    }
}

// ---------------- edge scatter: acc[dst] += h[src] * dis[src]*dis[dst] ----------------
__global__ void __launch_bounds__(256) k_scatter(const int* __restrict__ ei) {
    int e = blockIdx.x * 8 + (threadIdx.x >> 5);
    if (e >= Ee) return;
    int lane = threadIdx.x & 31;
    int s = ei[e], d = ei[Ee + e];
    float w = g_dis[s] * g_dis[d];
    const float4 v = *(const float4*)&g_h[(size_t)s * D + lane * 4];
    red4(&g_acc[(size_t)d * D + lane * 4], v.x * w, v.y * w, v.z * w, v.w * w);
}

// ---------------- host orchestration ----------------
extern "C" void kernel_launch(void* const* d_in, const int* in_sizes, int n_in,
                              void* d_out, int out_size)
{
    const float* node_feat = (const float*)d_in[0];
    const float* edge_feat = (const float*)d_in[1];
    const int*   ei        = (const int*)d_in[2];
    const float* enW1 = (const float*)d_in[3];  const float* enb1 = (const float*)d_in[4];
    const float* enW2 = (const float*)d_in[5];  const float* enb2 = (const float*)d_in[6];
    const float* enW3 = (const float*)d_in[7];  const float* enb3 = (const float*)d_in[8];
    const float* enlg = (const float*)d_in[9];  const float* enlb = (const float*)d_in[10];
    const float* eeW1 = (const float*)d_in[11]; const float* eeb1 = (const float*)d_in[12];
    const float* eeW2 = (const float*)d_in[13]; const float* eeb2 = (const float*)d_in[14];
    const float* eeW3 = (const float*)d_in[15]; const float* eeb3 = (const float*)d_in[16];
    const float* eelg = (const float*)d_in[17]; const float* eelb = (const float*)d_in[18];
    const float* procW = (const float*)d_in[19];
    const float* procb = (const float*)d_in[20];
    const float* bng   = (const float*)d_in[21];
    const float* bnb   = (const float*)d_in[22];
    const float* dW1 = (const float*)d_in[23]; const float* db1 = (const float*)d_in[24];
    const float* dW2 = (const float*)d_in[25]; const float* db2 = (const float*)d_in[26];
    const float* dW3 = (const float*)d_in[27]; const float* db3 = (const float*)d_in[28];
    const float* dlg = (const float*)d_in[29]; const float* dlb = (const float*)d_in[30];
    float* out = (float*)d_out;

    float* hn_ptr = nullptr;
    cudaGetSymbolAddress((void**)&hn_ptr, g_hn);

    auto mlp_smem = [](int kin) {
        int inb = (kin == D) ? 0 : 32 * kin;
        return (kin * D + 2 * D * D + 5 * D + inb + 32 * D) * (int)sizeof(float);
    };
    int smem_node = mlp_smem(NODE_IN);
    int smem_edge = mlp_smem(EDGE_IN);
    int smem_dec  = mlp_smem(D);
    int smem_conv = (D * D + 64 * D) * (int)sizeof(float);

    cudaFuncSetAttribute(k_mlp<NODE_IN, 0>, cudaFuncAttributeMaxDynamicSharedMemorySize, smem_node);
    cudaFuncSetAttribute(k_mlp<EDGE_IN, 1>, cudaFuncAttributeMaxDynamicSharedMemorySize, smem_edge);
    cudaFuncSetAttribute(k_mlp<D, 2>,       cudaFuncAttributeMaxDynamicSharedMemorySize, smem_dec);
    cudaFuncSetAttribute(k_gemm_conv,       cudaFuncAttributeMaxDynamicSharedMemorySize, smem_conv);

    // init + degrees
    k_zero<<<512, 256>>>();
    k_count<<<(Ee + 255) / 256, 256>>>(ei);
    k_dis<<<(Nn + 255) / 256, 256>>>();

    // encoders
    k_mlp<NODE_IN, 0><<<(Nn + 31) / 32, 256, smem_node>>>(
        node_feat, nullptr, enW1, enb1, enW2, enb2, enW3, enb3, enlg, enlb, hn_ptr, Nn);
    k_mlp<EDGE_IN, 1><<<(Ee + 31) / 32, 256, smem_edge>>>(
        edge_feat, ei, eeW1, eeb1, eeW2, eeb2, eeW3, eeb3, eelg, eelb, nullptr, Ee);
    k_mix<<<(Nn * D + 255) / 256, 256>>>();

    // processor steps
    for (int s = 0; s < STEPS; s++) {
        const float* W0 = procW + (size_t)(s * 2 + 0) * D * D;
        const float* W1 = procW + (size_t)(s * 2 + 1) * D * D;
        const float* b0 = procb + (size_t)(s * 2 + 0) * D;
        const float* b1 = procb + (size_t)(s * 2 + 1) * D;

        k_gemm_conv<<<(Nn + 63) / 64, 256, smem_conv>>>(hn_ptr, W0, 0);
        k_scatter<<<(Ee + 7) / 8, 256>>>(ei);
        k_bnzero<<<1, 128>>>();
        k_post1<<<512, 128>>>(b0);
        k_bnfin<<<1, 128>>>(bng + (size_t)s * D, bnb + (size_t)s * D);

        float* y_ptr = nullptr;
        cudaGetSymbolAddress((void**)&y_ptr, g_y);
        k_gemm_conv<<<(Nn + 63) / 64, 256, smem_conv>>>(y_ptr, W1, 1);
        k_scatter<<<(Ee + 7) / 8, 256>>>(ei);
        k_resid<<<(Nn * D + 255) / 256, 256>>>(b1);
    }

    // decoder
    k_mlp<D, 2><<<(Nn + 31) / 32, 256, smem_dec>>>(
        hn_ptr, nullptr, dW1, db1, dW2, db2, dW3, db3, dlg, dlb, out, Nn);
}

// round 2
// speedup vs baseline: 1.2432x; 1.2432x over previous
#include <cuda_runtime.h>
#include <cstddef>

#define Nn 50000
#define Ee 800000
#define D 128
#define NODE_IN 19
#define EDGE_IN 4
#define STEPS 5
#define EPSf 1e-5f

typedef unsigned long long u64;

// ---------------- device scratch ----------------
__device__ float g_hn[Nn * D];
__device__ float g_acc[Nn * D];
__device__ float g_h[Nn * D];
__device__ float g_y[Nn * D];
__device__ float g_cnt[Nn];
__device__ float g_dis[Nn];
__device__ float g_bnsum[D];
__device__ float g_bnsq[D];
__device__ float g_bnscale[D];
__device__ float g_bnshift[D];

__device__ __forceinline__ float leaky(float v) { return v > 0.f ? v : 0.05f * v; }

__device__ __forceinline__ void red4(float* p, float a, float b, float c, float d) {
    asm volatile("red.global.add.v4.f32 [%0], {%1,%2,%3,%4};"
                 :: "l"(p), "f"(a), "f"(b), "f"(c), "f"(d) : "memory");
}

// packed fp32x2 FMA: acc = x2 * w2 + acc (doubles FMA throughput vs FFMA-3reg)
__device__ __forceinline__ void ffma2(u64& acc, u64 x2, u64 w2) {
    asm("fma.rn.f32x2 %0, %1, %2, %0;" : "+l"(acc) : "l"(x2), "l"(w2));
}
__device__ __forceinline__ u64 packdup(float x) {
    u64 r; asm("mov.b64 %0, {%1, %1};" : "=l"(r) : "f"(x)); return r;
}
__device__ __forceinline__ float2 unpack2(u64 v) {
    float2 r; asm("mov.b64 {%0, %1}, %2;" : "=f"(r.x), "=f"(r.y) : "l"(v)); return r;
}

// ---------------- small utility kernels ----------------
__global__ void k_zero() {
    int i = blockIdx.x * blockDim.x + threadIdx.x;
    int stride = gridDim.x * blockDim.x;
    for (int j = i; j < Nn * D; j += stride) g_acc[j] = 0.f;
    for (int j = i; j < Nn; j += stride) { g_cnt[j] = 0.f; g_dis[j] = 0.f; }
}

__global__ void k_count(const int* __restrict__ ei) {
    int e = blockIdx.x * blockDim.x + threadIdx.x;
    if (e >= Ee) return;
    atomicAdd(&g_cnt[ei[e]], 1.f);
    atomicAdd(&g_dis[ei[Ee + e]], 1.f);
}

__global__ void k_dis() {
    int i = blockIdx.x * blockDim.x + threadIdx.x;
    if (i < Nn) g_dis[i] = rsqrtf(g_dis[i] + 1.0f);
}

__global__ void k_mix() {
    int i = blockIdx.x * blockDim.x + threadIdx.x;
    if (i < Nn * D) g_hn[i] += g_acc[i] / fmaxf(g_cnt[i >> 7], 1.f);
}

__global__ void k_bnzero() {
    int c = threadIdx.x;
    if (c < D) { g_bnsum[c] = 0.f; g_bnsq[c] = 0.f; }
}

__global__ void k_post1(const float* __restrict__ bias) {
    int c = threadIdx.x;
    float b = bias[c];
    float s = 0.f, q = 0.f;
    for (int row = blockIdx.x; row < Nn; row += gridDim.x) {
        float v = g_acc[(size_t)row * D + c] + b;
        v = leaky(v);
        g_y[(size_t)row * D + c] = v;
        s += v; q += v * v;
    }
    atomicAdd(&g_bnsum[c], s);
    atomicAdd(&g_bnsq[c], q);
}

__global__ void k_bnfin(const float* __restrict__ g, const float* __restrict__ b) {
    int c = threadIdx.x;
    if (c < D) {
        float m = g_bnsum[c] * (1.f / (float)Nn);
        float v = g_bnsq[c] * (1.f / (float)Nn) - m * m;
        float sc = g[c] * rsqrtf(v + EPSf);
        g_bnscale[c] = sc;
        g_bnshift[c] = b[c] - m * sc;
    }
}

__global__ void k_resid(const float* __restrict__ bias) {
    int i = blockIdx.x * blockDim.x + threadIdx.x;
    if (i < Nn * D) g_hn[i] += g_acc[i] + bias[i & (D - 1)];
}

// ---------------- fused MLP3 + LayerNorm (8 rows/warp, f32x2 packed FMA) ----------------
// MODE 0: write out (node enc -> g_hn); MODE 1: red4 scatter to g_acc[esrc[row]];
// MODE 2: write out (decoder)
template <int KIN, int MODE>
__global__ void __launch_bounds__(256) k_mlp(
    const float* __restrict__ in, const int* __restrict__ esrc,
    const float* __restrict__ W1, const float* __restrict__ b1,
    const float* __restrict__ W2, const float* __restrict__ b2,
    const float* __restrict__ W3, const float* __restrict__ b3,
    const float* __restrict__ lng, const float* __restrict__ lnb,
    float* __restrict__ out, int M)
{
    constexpr int KINP = (KIN + 3) & ~3;           // pad K to multiple of 4
    extern __shared__ float sh[];
    float* W1s = sh;                               // KINP * D (pad rows zeroed)
    float* W2s = W1s + KINP * D;
    float* W3s = W2s + D * D;
    float* cst = W3s + D * D;                      // b1,b2,b3,g,b : 5*D
    float* inb = cst + 5 * D;
    constexpr int INB = (KIN == D) ? 0 : 64 * KINP;
    float* rb = inb + INB;                         // 8 warps * 8 rows * D

    int tid = threadIdx.x, lane = tid & 31, wid = tid >> 5;

    for (int i = tid; i < KIN * D / 4; i += 256)
        ((float4*)W1s)[i] = ((const float4*)W1)[i];
    if (KINP > KIN)
        for (int i = KIN * D / 4 + tid; i < KINP * D / 4; i += 256)
            ((float4*)W1s)[i] = make_float4(0.f, 0.f, 0.f, 0.f);
    for (int i = tid; i < D * D / 4; i += 256) {
        ((float4*)W2s)[i] = ((const float4*)W2)[i];
        ((float4*)W3s)[i] = ((const float4*)W3)[i];
    }
    if (tid < D) {
        cst[tid] = b1[tid]; cst[D + tid] = b2[tid]; cst[2 * D + tid] = b3[tid];
        cst[3 * D + tid] = lng[tid]; cst[4 * D + tid] = lnb[tid];
    }
    __syncthreads();

    int rowbase = (blockIdx.x * 8 + wid) * 8;
    float* myrb = rb + wid * (8 * D);
    float* myin = (KIN == D) ? myrb : (inb + wid * (8 * KINP));

    #pragma unroll
    for (int r = 0; r < 8; r++) {
        int row = min(rowbase + r, M - 1);
        for (int k = lane; k < KINP; k += 32)
            myin[r * KINP + k] = (k < KIN) ? in[(size_t)row * KIN + k] : 0.f;
    }
    __syncwarp();

    int c0 = lane * 4;
    u64 a01[8], a23[8];
    ulonglong2 bini;

    // ---- layer 1 ----
    bini = *(const ulonglong2*)&cst[c0];
    #pragma unroll
    for (int r = 0; r < 8; r++) { a01[r] = bini.x; a23[r] = bini.y; }
    for (int k0 = 0; k0 < KINP; k0 += 4) {
        u64 w01[4], w23[4];
        #pragma unroll
        for (int kk = 0; kk < 4; kk++) {
            ulonglong2 wv = *(const ulonglong2*)&W1s[(k0 + kk) * D + c0];
            w01[kk] = wv.x; w23[kk] = wv.y;
        }
        #pragma unroll
        for (int r = 0; r < 8; r++) {
            float4 xb = *(const float4*)&myin[r * KINP + k0];
            u64 x0 = packdup(xb.x), x1 = packdup(xb.y), x2 = packdup(xb.z), x3 = packdup(xb.w);
            ffma2(a01[r], x0, w01[0]); ffma2(a23[r], x0, w23[0]);
            ffma2(a01[r], x1, w01[1]); ffma2(a23[r], x1, w23[1]);
            ffma2(a01[r], x2, w01[2]); ffma2(a23[r], x2, w23[2]);
            ffma2(a01[r], x3, w01[3]); ffma2(a23[r], x3, w23[3]);
        }
    }
    __syncwarp();
    #pragma unroll
    for (int r = 0; r < 8; r++) {
        float2 v01 = unpack2(a01[r]), v23 = unpack2(a23[r]);
        float4 o = make_float4(leaky(v01.x), leaky(v01.y), leaky(v23.x), leaky(v23.y));
        *(float4*)&myrb[r * D + c0] = o;
    }
    __syncwarp();

    // ---- layer 2 ----
    bini = *(const ulonglong2*)&cst[D + c0];
    #pragma unroll
    for (int r = 0; r < 8; r++) { a01[r] = bini.x; a23[r] = bini.y; }
    #pragma unroll 2
    for (int k0 = 0; k0 < D; k0 += 4) {
        u64 w01[4], w23[4];
        #pragma unroll
        for (int kk = 0; kk < 4; kk++) {
            ulonglong2 wv = *(const ulonglong2*)&W2s[(k0 + kk) * D + c0];
            w01[kk] = wv.x; w23[kk] = wv.y;
        }
        #pragma unroll
        for (int r = 0; r < 8; r++) {
            float4 xb = *(const float4*)&myrb[r * D + k0];
            u64 x0 = packdup(xb.x), x1 = packdup(xb.y), x2 = packdup(xb.z), x3 = packdup(xb.w);
            ffma2(a01[r], x0, w01[0]); ffma2(a23[r], x0, w23[0]);
            ffma2(a01[r], x1, w01[1]); ffma2(a23[r], x1, w23[1]);
            ffma2(a01[r], x2, w01[2]); ffma2(a23[r], x2, w23[2]);
            ffma2(a01[r], x3, w01[3]); ffma2(a23[r], x3, w23[3]);
        }
    }
    __syncwarp();
    #pragma unroll
    for (int r = 0; r < 8; r++) {
        float2 v01 = unpack2(a01[r]), v23 = unpack2(a23[r]);
        float4 o = make_float4(leaky(v01.x), leaky(v01.y), leaky(v23.x), leaky(v23.y));
        *(float4*)&myrb[r * D + c0] = o;
    }
    __syncwarp();

    // ---- layer 3 ----
    bini = *(const ulonglong2*)&cst[2 * D + c0];
    #pragma unroll
    for (int r = 0; r < 8; r++) { a01[r] = bini.x; a23[r] = bini.y; }
    #pragma unroll 2
    for (int k0 = 0; k0 < D; k0 += 4) {
        u64 w01[4], w23[4];
        #pragma unroll
        for (int kk = 0; kk < 4; kk++) {
            ulonglong2 wv = *(const ulonglong2*)&W3s[(k0 + kk) * D + c0];
            w01[kk] = wv.x; w23[kk] = wv.y;
        }
        #pragma unroll
        for (int r = 0; r < 8; r++) {
            float4 xb = *(const float4*)&myrb[r * D + k0];
            u64 x0 = packdup(xb.x), x1 = packdup(xb.y), x2 = packdup(xb.z), x3 = packdup(xb.w);
            ffma2(a01[r], x0, w01[0]); ffma2(a23[r], x0, w23[0]);
            ffma2(a01[r], x1, w01[1]); ffma2(a23[r], x1, w23[1]);
            ffma2(a01[r], x2, w01[2]); ffma2(a23[r], x2, w23[2]);
            ffma2(a01[r], x3, w01[3]); ffma2(a23[r], x3, w23[3]);
        }
    }

    // ---- LayerNorm + emit ----
    #pragma unroll
    for (int r = 0; r < 8; r++) {
        float2 v01 = unpack2(a01[r]), v23 = unpack2(a23[r]);
        float a0 = v01.x, a1 = v01.y, a2 = v23.x, a3 = v23.y;
        float s = a0 + a1 + a2 + a3;
        float q = a0*a0 + a1*a1 + a2*a2 + a3*a3;
        #pragma unroll
        for (int off = 16; off > 0; off >>= 1) {
            s += __shfl_xor_sync(0xffffffffu, s, off);
            q += __shfl_xor_sync(0xffffffffu, q, off);
        }
        float m = s * (1.0f / (float)D);
        float var = q * (1.0f / (float)D) - m * m;
        float inv = rsqrtf(var + EPSf);
        int row = rowbase + r;
        if (row < M) {
            float o0 = (a0 - m) * inv * cst[3 * D + c0 + 0] + cst[4 * D + c0 + 0];
            float o1 = (a1 - m) * inv * cst[3 * D + c0 + 1] + cst[4 * D + c0 + 1];
            float o2 = (a2 - m) * inv * cst[3 * D + c0 + 2] + cst[4 * D + c0 + 2];
            float o3 = (a3 - m) * inv * cst[3 * D + c0 + 3] + cst[4 * D + c0 + 3];
            if (MODE == 1) {
                int sidx = esrc[row];
                red4(&g_acc[(size_t)sidx * D + c0], o0, o1, o2, o3);
            } else {
                *(float4*)&out[(size_t)row * D + c0] = make_float4(o0, o1, o2, o3);
            }
        }
    }
}

// ---------------- conv GEMM: h = f(x) @ W ; acc = h * dis^2 ----------------
__global__ void __launch_bounds__(256) k_gemm_conv(
    const float* __restrict__ x, const float* __restrict__ W, int use_bn)
{
    extern __shared__ float sh[];
    float* Ws = sh;               // D*D
    float* rb = sh + D * D;       // 8 warps * 8 rows * D
    int tid = threadIdx.x, lane = tid & 31, wid = tid >> 5;
    int c0 = lane * 4;

    for (int i = tid; i < D * D / 4; i += 256)
        ((float4*)Ws)[i] = ((const float4*)W)[i];

    float sc[4], sf[4];
    if (use_bn) {
        #pragma unroll
        for (int j = 0; j < 4; j++) { sc[j] = g_bnscale[c0 + j]; sf[j] = g_bnshift[c0 + j]; }
    }
    __syncthreads();

    int rowbase = (blockIdx.x * 8 + wid) * 8;
    float* myrb = rb + wid * (8 * D);
    #pragma unroll
    for (int r = 0; r < 8; r++) {
        int row = min(rowbase + r, Nn - 1);
        float4 v = *(const float4*)&x[(size_t)row * D + c0];
        if (use_bn) {
            v.x = fmaf(v.x, sc[0], sf[0]); v.y = fmaf(v.y, sc[1], sf[1]);
            v.z = fmaf(v.z, sc[2], sf[2]); v.w = fmaf(v.w, sc[3], sf[3]);
        }
        *(float4*)&myrb[r * D + c0] = v;
    }
    __syncwarp();

    u64 a01[8], a23[8];
    #pragma unroll
    for (int r = 0; r < 8; r++) { a01[r] = 0ull; a23[r] = 0ull; }

    #pragma unroll 2
    for (int k0 = 0; k0 < D; k0 += 4) {
        u64 w01[4], w23[4];
        #pragma unroll
        for (int kk = 0; kk < 4; kk++) {
            ulonglong2 wv = *(const ulonglong2*)&Ws[(k0 + kk) * D + c0];
            w01[kk] = wv.x; w23[kk] = wv.y;
        }
        #pragma unroll
        for (int r = 0; r < 8; r++) {
            float4 xb = *(const float4*)&myrb[r * D + k0];
            u64 x0 = packdup(xb.x), x1 = packdup(xb.y), x2 = packdup(xb.z), x3 = packdup(xb.w);
            ffma2(a01[r], x0, w01[0]); ffma2(a23[r], x0, w23[0]);
            ffma2(a01[r], x1, w01[1]); ffma2(a23[r], x1, w23[1]);
            ffma2(a01[r], x2, w01[2]); ffma2(a23[r], x2, w23[2]);
            ffma2(a01[r], x3, w01[3]); ffma2(a23[r], x3, w23[3]);
        }
    }

    #pragma unroll
    for (int r = 0; r < 8; r++) {
        int row = rowbase + r;
        if (row < Nn) {
            float2 v01 = unpack2(a01[r]), v23 = unpack2(a23[r]);
            float dd = g_dis[row];
            float d2 = dd * dd;
            *(float4*)&g_h[(size_t)row * D + c0] = make_float4(v01.x, v01.y, v23.x, v23.y);
            *(float4*)&g_acc[(size_t)row * D + c0] =
                make_float4(v01.x * d2, v01.y * d2, v23.x * d2, v23.y * d2);
        }
    }
}

// ---------------- edge scatter: acc[dst] += h[src] * dis[src]*dis[dst] ----------------
__global__ void __launch_bounds__(256) k_scatter(const int* __restrict__ ei) {
    int e = blockIdx.x * 8 + (threadIdx.x >> 5);
    if (e >= Ee) return;
    int lane = threadIdx.x & 31;
    int s = ei[e], d = ei[Ee + e];
    float w = g_dis[s] * g_dis[d];
    const float4 v = *(const float4*)&g_h[(size_t)s * D + lane * 4];
    red4(&g_acc[(size_t)d * D + lane * 4], v.x * w, v.y * w, v.z * w, v.w * w);
}

// ---------------- host orchestration ----------------
extern "C" void kernel_launch(void* const* d_in, const int* in_sizes, int n_in,
                              void* d_out, int out_size)
{
    const float* node_feat = (const float*)d_in[0];
    const float* edge_feat = (const float*)d_in[1];
    const int*   ei        = (const int*)d_in[2];
    const float* enW1 = (const float*)d_in[3];  const float* enb1 = (const float*)d_in[4];
    const float* enW2 = (const float*)d_in[5];  const float* enb2 = (const float*)d_in[6];
    const float* enW3 = (const float*)d_in[7];  const float* enb3 = (const float*)d_in[8];
    const float* enlg = (const float*)d_in[9];  const float* enlb = (const float*)d_in[10];
    const float* eeW1 = (const float*)d_in[11]; const float* eeb1 = (const float*)d_in[12];
    const float* eeW2 = (const float*)d_in[13]; const float* eeb2 = (const float*)d_in[14];
    const float* eeW3 = (const float*)d_in[15]; const float* eeb3 = (const float*)d_in[16];
    const float* eelg = (const float*)d_in[17]; const float* eelb = (const float*)d_in[18];
    const float* procW = (const float*)d_in[19];
    const float* procb = (const float*)d_in[20];
    const float* bng   = (const float*)d_in[21];
    const float* bnb   = (const float*)d_in[22];
    const float* dW1 = (const float*)d_in[23]; const float* db1 = (const float*)d_in[24];
    const float* dW2 = (const float*)d_in[25]; const float* db2 = (const float*)d_in[26];
    const float* dW3 = (const float*)d_in[27]; const float* db3 = (const float*)d_in[28];
    const float* dlg = (const float*)d_in[29]; const float* dlb = (const float*)d_in[30];
    float* out = (float*)d_out;

    float* hn_ptr = nullptr;
    cudaGetSymbolAddress((void**)&hn_ptr, g_hn);
    float* y_ptr = nullptr;
    cudaGetSymbolAddress((void**)&y_ptr, g_y);

    auto mlp_smem = [](int kin) {
        int kinp = (kin + 3) & ~3;
        int inb = (kin == D) ? 0 : 64 * kinp;
        return (kinp * D + 2 * D * D + 5 * D + inb + 64 * D) * (int)sizeof(float);
    };
    int smem_node = mlp_smem(NODE_IN);
    int smem_edge = mlp_smem(EDGE_IN);
    int smem_dec  = mlp_smem(D);
    int smem_conv = (D * D + 64 * D) * (int)sizeof(float);

    cudaFuncSetAttribute(k_mlp<NODE_IN, 0>, cudaFuncAttributeMaxDynamicSharedMemorySize, smem_node);
    cudaFuncSetAttribute(k_mlp<EDGE_IN, 1>, cudaFuncAttributeMaxDynamicSharedMemorySize, smem_edge);
    cudaFuncSetAttribute(k_mlp<D, 2>,       cudaFuncAttributeMaxDynamicSharedMemorySize, smem_dec);
    cudaFuncSetAttribute(k_gemm_conv,       cudaFuncAttributeMaxDynamicSharedMemorySize, smem_conv);

    // init + degrees
    k_zero<<<512, 256>>>();
    k_count<<<(Ee + 255) / 256, 256>>>(ei);
    k_dis<<<(Nn + 255) / 256, 256>>>();

    // encoders (64 rows per block)
    k_mlp<NODE_IN, 0><<<(Nn + 63) / 64, 256, smem_node>>>(
        node_feat, nullptr, enW1, enb1, enW2, enb2, enW3, enb3, enlg, enlb, hn_ptr, Nn);
    k_mlp<EDGE_IN, 1><<<(Ee + 63) / 64, 256, smem_edge>>>(
        edge_feat, ei, eeW1, eeb1, eeW2, eeb2, eeW3, eeb3, eelg, eelb, nullptr, Ee);
    k_mix<<<(Nn * D + 255) / 256, 256>>>();

    // processor steps
    for (int s = 0; s < STEPS; s++) {
        const float* W0 = procW + (size_t)(s * 2 + 0) * D * D;
        const float* W1 = procW + (size_t)(s * 2 + 1) * D * D;
        const float* b0 = procb + (size_t)(s * 2 + 0) * D;
        const float* b1 = procb + (size_t)(s * 2 + 1) * D;

        k_gemm_conv<<<(Nn + 63) / 64, 256, smem_conv>>>(hn_ptr, W0, 0);
        k_scatter<<<(Ee + 7) / 8, 256>>>(ei);
        k_bnzero<<<1, 128>>>();
        k_post1<<<512, 128>>>(b0);
        k_bnfin<<<1, 128>>>(bng + (size_t)s * D, bnb + (size_t)s * D);

        k_gemm_conv<<<(Nn + 63) / 64, 256, smem_conv>>>(y_ptr, W1, 1);
        k_scatter<<<(Ee + 7) / 8, 256>>>(ei);
        k_resid<<<(Nn * D + 255) / 256, 256>>>(b1);
    }

    // decoder
    k_mlp<D, 2><<<(Nn + 63) / 64, 256, smem_dec>>>(
        hn_ptr, nullptr, dW1, db1, dW2, db2, dW3, db3, dlg, dlb, out, Nn);
}

// round 4
// speedup vs baseline: 1.2593x; 1.0129x over previous
#include <cuda_runtime.h>
#include <cuda_bf16.h>
#include <mma.h>
#include <cstddef>
#include <cstdint>

using namespace nvcuda;

#define Nn 50000
#define Ee 800000
#define D 128
#define NODE_IN 19
#define EDGE_IN 4
#define STEPS 5
#define EPSf 1e-5f

typedef unsigned long long u64;
typedef unsigned int u32;

// ---------------- device scratch ----------------
__device__ float g_hn[Nn * D];
__device__ float g_acc[Nn * D];
__device__ float g_h[Nn * D];
__device__ float g_y[Nn * D];
__device__ float g_cnt[Nn];
__device__ float g_dis[Nn];
__device__ float g_bnsum[D];
__device__ float g_bnsq[D];
__device__ float g_bnscale[D];
__device__ float g_bnshift[D];

// bf16 split activation buffers (double-buffered), sized for edges
__device__ __nv_bfloat16 g_bhi[(size_t)Ee * D];
__device__ __nv_bfloat16 g_blo[(size_t)Ee * D];
__device__ __nv_bfloat16 g_chi[(size_t)Ee * D];
__device__ __nv_bfloat16 g_clo[(size_t)Ee * D];

// split+transposed weights [slot][n][k], 17 slots
#define NSLOT 17
__device__ __nv_bfloat16 g_whi[NSLOT * D * D];
__device__ __nv_bfloat16 g_wlo[NSLOT * D * D];

__device__ __forceinline__ float leaky(float v) { return v > 0.f ? v : 0.05f * v; }

__device__ __forceinline__ void red4(float* p, float a, float b, float c, float d) {
    asm volatile("red.global.add.v4.f32 [%0], {%1,%2,%3,%4};"
                 :: "l"(p), "f"(a), "f"(b), "f"(c), "f"(d) : "memory");
}

// packed fp32x2 FMA (for layer-1 kernels)
__device__ __forceinline__ void ffma2(u64& acc, u64 x2, u64 w2) {
    asm("fma.rn.f32x2 %0, %1, %2, %0;" : "+l"(acc) : "l"(x2), "l"(w2));
}
__device__ __forceinline__ u64 packdup(float x) {
    u64 r; asm("mov.b64 %0, {%1, %1};" : "=l"(r) : "f"(x)); return r;
}
__device__ __forceinline__ float2 unpack2(u64 v) {
    float2 r; asm("mov.b64 {%0, %1}, %2;" : "=f"(r.x), "=f"(r.y) : "l"(v)); return r;
}
__device__ __forceinline__ u32 bfpack(__nv_bfloat16 a, __nv_bfloat16 b) {
    __nv_bfloat162 t = __halves2bfloat162(a, b);
    return *(u32*)&t;
}

// ---------------- utility kernels ----------------
__global__ void k_zero() {
    int i = blockIdx.x * blockDim.x + threadIdx.x;
    int stride = gridDim.x * blockDim.x;
    for (int j = i; j < Nn * D; j += stride) g_acc[j] = 0.f;
    for (int j = i; j < Nn; j += stride) { g_cnt[j] = 0.f; g_dis[j] = 0.f; }
}

__global__ void k_count(const int* __restrict__ ei) {
    int e = blockIdx.x * blockDim.x + threadIdx.x;
    if (e >= Ee) return;
    atomicAdd(&g_cnt[ei[e]], 1.f);
    atomicAdd(&g_dis[ei[Ee + e]], 1.f);
}

__global__ void k_dis() {
    int i = blockIdx.x * blockDim.x + threadIdx.x;
    if (i < Nn) g_dis[i] = rsqrtf(g_dis[i] + 1.0f);
}

__global__ void k_mix() {
    int i = blockIdx.x * blockDim.x + threadIdx.x;
    if (i < Nn * D) g_hn[i] += g_acc[i] / fmaxf(g_cnt[i >> 7], 1.f);
}

__global__ void k_bnzero() {
    int c = threadIdx.x;
    if (c < D) { g_bnsum[c] = 0.f; g_bnsq[c] = 0.f; }
}

__global__ void k_post1(const float* __restrict__ bias) {
    int c = threadIdx.x;
    float b = bias[c];
    float s = 0.f, q = 0.f;
    for (int row = blockIdx.x; row < Nn; row += gridDim.x) {
        float v = g_acc[(size_t)row * D + c] + b;
        v = leaky(v);
        g_y[(size_t)row * D + c] = v;
        s += v; q += v * v;
    }
    atomicAdd(&g_bnsum[c], s);
    atomicAdd(&g_bnsq[c], q);
}

__global__ void k_bnfin(const float* __restrict__ g, const float* __restrict__ b) {
    int c = threadIdx.x;
    if (c < D) {
        float m = g_bnsum[c] * (1.f / (float)Nn);
        float v = g_bnsq[c] * (1.f / (float)Nn) - m * m;
        float sc = g[c] * rsqrtf(v + EPSf);
        g_bnscale[c] = sc;
        g_bnshift[c] = b[c] - m * sc;
    }
}

__global__ void k_resid(const float* __restrict__ bias) {
    int i = blockIdx.x * blockDim.x + threadIdx.x;
    if (i < Nn * D) g_hn[i] += g_acc[i] + bias[i & (D - 1)];
}

// fp32 -> bf16 hi/lo split (elementwise)
__global__ void k_split(const float* __restrict__ x, __nv_bfloat16* __restrict__ hi,
                        __nv_bfloat16* __restrict__ lo, int n) {
    int i = blockIdx.x * blockDim.x + threadIdx.x;
    if (i >= n) return;
    float v = x[i];
    __nv_bfloat16 h = __float2bfloat16(v);
    hi[i] = h;
    lo[i] = __float2bfloat16(v - __bfloat162float(h));
}

// y -> BN affine -> split
__global__ void k_split_bn(const float* __restrict__ x, __nv_bfloat16* __restrict__ hi,
                           __nv_bfloat16* __restrict__ lo, int n) {
    int i = blockIdx.x * blockDim.x + threadIdx.x;
    if (i >= n) return;
    int c = i & (D - 1);
    float v = fmaf(x[i], g_bnscale[c], g_bnshift[c]);
    __nv_bfloat16 h = __float2bfloat16(v);
    hi[i] = h;
    lo[i] = __float2bfloat16(v - __bfloat162float(h));
}

// weight split + transpose: W[k][n] fp32 -> whi/wlo[slot][n][k]
__global__ void k_wsplit(const float* __restrict__ W, int slot) {
    int i = blockIdx.x * 256 + threadIdx.x;   // 64 blocks x 256 = 16384
    int k = i >> 7, n = i & 127;
    float v = W[i];
    __nv_bfloat16 h = __float2bfloat16(v);
    g_whi[slot * D * D + n * D + k] = h;
    g_wlo[slot * D * D + n * D + k] = __float2bfloat16(v - __bfloat162float(h));
}

// ---------------- layer-1 (small K) + split output ----------------
template <int KIN>
__global__ void __launch_bounds__(256) k_lin1(
    const float* __restrict__ in, const float* __restrict__ W1,
    const float* __restrict__ b1,
    __nv_bfloat16* __restrict__ yhi, __nv_bfloat16* __restrict__ ylo, int M)
{
    constexpr int KINP = (KIN + 3) & ~3;
    extern __shared__ float sh[];
    float* W1s = sh;                 // KINP * D
    float* cst = W1s + KINP * D;     // D
    float* inb = cst + D;            // 8 warps * 8 rows * KINP

    int tid = threadIdx.x, lane = tid & 31, wid = tid >> 5;
    for (int i = tid; i < KIN * D / 4; i += 256)
        ((float4*)W1s)[i] = ((const float4*)W1)[i];
    if (KINP > KIN)
        for (int i = KIN * D / 4 + tid; i < KINP * D / 4; i += 256)
            ((float4*)W1s)[i] = make_float4(0.f, 0.f, 0.f, 0.f);
    if (tid < D) cst[tid] = b1[tid];
    __syncthreads();

    int rowbase = (blockIdx.x * 8 + wid) * 8;
    float* myin = inb + wid * (8 * KINP);
    #pragma unroll
    for (int r = 0; r < 8; r++) {
        int row = min(rowbase + r, M - 1);
        for (int k = lane; k < KINP; k += 32)
            myin[r * KINP + k] = (k < KIN) ? in[(size_t)row * KIN + k] : 0.f;
    }
    __syncwarp();

    int c0 = lane * 4;
    u64 a01[8], a23[8];
    ulonglong2 bini = *(const ulonglong2*)&cst[c0];
    #pragma unroll
    for (int r = 0; r < 8; r++) { a01[r] = bini.x; a23[r] = bini.y; }

    for (int k0 = 0; k0 < KINP; k0 += 4) {
        u64 w01[4], w23[4];
        #pragma unroll
        for (int kk = 0; kk < 4; kk++) {
            ulonglong2 wv = *(const ulonglong2*)&W1s[(k0 + kk) * D + c0];
            w01[kk] = wv.x; w23[kk] = wv.y;
        }
        #pragma unroll
        for (int r = 0; r < 8; r++) {
            float4 xb = *(const float4*)&myin[r * KINP + k0];
            u64 x0 = packdup(xb.x), x1 = packdup(xb.y), x2 = packdup(xb.z), x3 = packdup(xb.w);
            ffma2(a01[r], x0, w01[0]); ffma2(a23[r], x0, w23[0]);
            ffma2(a01[r], x1, w01[1]); ffma2(a23[r], x1, w23[1]);
            ffma2(a01[r], x2, w01[2]); ffma2(a23[r], x2, w23[2]);
            ffma2(a01[r], x3, w01[3]); ffma2(a23[r], x3, w23[3]);
        }
    }

    #pragma unroll
    for (int r = 0; r < 8; r++) {
        int row = rowbase + r;
        if (row >= M) break;
        float2 v01 = unpack2(a01[r]), v23 = unpack2(a23[r]);
        float z0 = leaky(v01.x), z1 = leaky(v01.y), z2 = leaky(v23.x), z3 = leaky(v23.y);
        __nv_bfloat16 h0 = __float2bfloat16(z0), h1 = __float2bfloat16(z1);
        __nv_bfloat16 h2 = __float2bfloat16(z2), h3 = __float2bfloat16(z3);
        u32 hi01 = bfpack(h0, h1), hi23 = bfpack(h2, h3);
        u32 lo01 = bfpack(__float2bfloat16(z0 - __bfloat162float(h0)),
                          __float2bfloat16(z1 - __bfloat162float(h1)));
        u32 lo23 = bfpack(__float2bfloat16(z2 - __bfloat162float(h2)),
                          __float2bfloat16(z3 - __bfloat162float(h3)));
        *(uint2*)&yhi[(size_t)row * D + c0] = make_uint2(hi01, hi23);
        *(uint2*)&ylo[(size_t)row * D + c0] = make_uint2(lo01, lo23);
    }
}

// ---------------- WMMA GEMM, tile = 128 rows x 128 cols, K = 128 ----------------
// smem layout (bytes):
#define LDA 136                     // bf16 elements per row (padded)
#define LDS_F 136                   // fp32 stage stride
#define OFF_AH 0
#define OFF_AL 34816
#define OFF_WH 69632
#define OFF_WL 104448
#define OFF_STG 139264              // fp32 [128][136] = 69632 B
#define OFF_CST 208896              // bias | lng | lnb : 3 * 512 B
#define SMEM_MMA 210432

// EPI: 0 = HID (bias+leaky, split out), 1 = LN (bias+LN, fp32 out),
//      2 = LNSC (bias+LN, red4 scatter to g_acc[esrc]), 3 = CONV (g_h, g_acc=h*dis^2)
template <int EPI>
__global__ void __launch_bounds__(256, 1) k_wgemm(
    const __nv_bfloat16* __restrict__ xhi, const __nv_bfloat16* __restrict__ xlo,
    int slot, const float* __restrict__ bias,
    const float* __restrict__ lng, const float* __restrict__ lnb,
    float* __restrict__ out,
    __nv_bfloat16* __restrict__ yhi, __nv_bfloat16* __restrict__ ylo,
    const int* __restrict__ esrc, int M)
{
    extern __shared__ char smem[];
    int tid = threadIdx.x, wid = tid >> 5;
    int tb = blockIdx.x * 128;

    __nv_bfloat16* Ah = (__nv_bfloat16*)(smem + OFF_AH);
    __nv_bfloat16* Al = (__nv_bfloat16*)(smem + OFF_AL);
    __nv_bfloat16* Wh = (__nv_bfloat16*)(smem + OFF_WH);
    __nv_bfloat16* Wl = (__nv_bfloat16*)(smem + OFF_WL);
    float* stg  = (float*)(smem + OFF_STG);
    float* cstb = (float*)(smem + OFF_CST);
    float* cstg = (float*)(smem + OFF_CST + 512);
    float* cstl = (float*)(smem + OFF_CST + 1024);

    // stage A (hi/lo) rows and W (hi/lo) rows into padded smem
    const uint4* pxh = (const uint4*)xhi;
    const uint4* pxl = (const uint4*)xlo;
    const uint4* pwh = ((const uint4*)g_whi) + (size_t)slot * 2048;
    const uint4* pwl = ((const uint4*)g_wlo) + (size_t)slot * 2048;
    for (int i = tid; i < 2048; i += 256) {
        int row = i >> 4, c = i & 15;               // c = 16-byte chunk (8 bf16)
        int gr = min(tb + row, M - 1);
        *(uint4*)&Ah[row * LDA + c * 8] = pxh[(size_t)gr * 16 + c];
        *(uint4*)&Al[row * LDA + c * 8] = pxl[(size_t)gr * 16 + c];
        *(uint4*)&Wh[row * LDA + c * 8] = pwh[row * 16 + c];
        *(uint4*)&Wl[row * LDA + c * 8] = pwl[row * 16 + c];
    }
    if (EPI != 3 && tid < D) cstb[tid] = bias[tid];
    if ((EPI == 1 || EPI == 2) && tid < D) { cstg[tid] = lng[tid]; cstl[tid] = lnb[tid]; }
    __syncthreads();

    // warp grid: 4 row-blocks x 2 col-blocks; each warp 32 rows x 64 cols
    int wr = wid & 3, wc = wid >> 2;

    wmma::fragment<wmma::accumulator, 16, 16, 16, float> acc[2][4];
    #pragma unroll
    for (int i = 0; i < 2; i++)
        #pragma unroll
        for (int j = 0; j < 4; j++) wmma::fill_fragment(acc[i][j], 0.f);

    const __nv_bfloat16* Ap[3] = {Ah, Ah, Al};
    const __nv_bfloat16* Wp[3] = {Wh, Wl, Wh};

    #pragma unroll
    for (int p = 0; p < 3; p++) {
        const __nv_bfloat16* A = Ap[p];
        const __nv_bfloat16* W = Wp[p];
        #pragma unroll
        for (int k = 0; k < 8; k++) {
            wmma::fragment<wmma::matrix_a, 16, 16, 16, __nv_bfloat16, wmma::row_major> af[2];
            wmma::fragment<wmma::matrix_b, 16, 16, 16, __nv_bfloat16, wmma::col_major> bfr[4];
            wmma::load_matrix_sync(af[0], &A[(wr * 32) * LDA + k * 16], LDA);
            wmma::load_matrix_sync(af[1], &A[(wr * 32 + 16) * LDA + k * 16], LDA);
            #pragma unroll
            for (int j = 0; j < 4; j++)
                wmma::load_matrix_sync(bfr[j], &W[(wc * 64 + j * 16) * LDA + k * 16], LDA);
            #pragma unroll
            for (int i = 0; i < 2; i++)
                #pragma unroll
                for (int j = 0; j < 4; j++)
                    wmma::mma_sync(acc[i][j], af[i], bfr[j], acc[i][j]);
        }
    }

    #pragma unroll
    for (int i = 0; i < 2; i++)
        #pragma unroll
        for (int j = 0; j < 4; j++)
            wmma::store_matrix_sync(&stg[(wr * 32 + i * 16) * LDS_F + wc * 64 + j * 16],
                                    acc[i][j], LDS_F, wmma::mem_row_major);
    __syncthreads();

    // ---- epilogue: 2 threads per row, each handles 64 cols ----
    int r = tid >> 1, half = tid & 1;
    int cb = half * 64;
    int grow = tb + r;
    bool valid = grow < M;
    const float* srow = &stg[r * LDS_F + cb];

    if (EPI == 0) {   // bias + leaky -> bf16 hi/lo
        #pragma unroll
        for (int j0 = 0; j0 < 64; j0 += 8) {
            u32 hi[4], lo[4];
            #pragma unroll
            for (int jj = 0; jj < 8; jj += 2) {
                int c = cb + j0 + jj;
                float z0 = leaky(srow[j0 + jj] + cstb[c]);
                float z1 = leaky(srow[j0 + jj + 1] + cstb[c + 1]);
                __nv_bfloat16 h0 = __float2bfloat16(z0), h1 = __float2bfloat16(z1);
                hi[jj >> 1] = bfpack(h0, h1);
                lo[jj >> 1] = bfpack(__float2bfloat16(z0 - __bfloat162float(h0)),
                                     __float2bfloat16(z1 - __bfloat162float(h1)));
            }
            if (valid) {
                *(uint4*)&yhi[(size_t)grow * D + cb + j0] = make_uint4(hi[0], hi[1], hi[2], hi[3]);
                *(uint4*)&ylo[(size_t)grow * D + cb + j0] = make_uint4(lo[0], lo[1], lo[2], lo[3]);
            }
        }
    } else if (EPI == 1 || EPI == 2) {   // LayerNorm (+ scatter)
        float s = 0.f, q = 0.f;
        #pragma unroll
        for (int j = 0; j < 64; j++) {
            float z = srow[j] + cstb[cb + j];
            s += z; q += z * z;
        }
        s += __shfl_xor_sync(0xffffffffu, s, 1);
        q += __shfl_xor_sync(0xffffffffu, q, 1);
        float m = s * (1.f / (float)D);
        float var = q * (1.f / (float)D) - m * m;
        float inv = rsqrtf(var + EPSf);
        int sidx = (EPI == 2 && valid) ? esrc[grow] : 0;
        #pragma unroll
        for (int j0 = 0; j0 < 64; j0 += 4) {
            float o[4];
            #pragma unroll
            for (int jj = 0; jj < 4; jj++) {
                int c = cb + j0 + jj;
                float z = srow[j0 + jj] + cstb[c];
                o[jj] = (z - m) * inv * cstg[c] + cstl[c];
            }
            if (EPI == 2) {
                if (valid)
                    red4(&g_acc[(size_t)sidx * D + cb + j0], o[0], o[1], o[2], o[3]);
            } else if (valid) {
                *(float4*)&out[(size_t)grow * D + cb + j0] = make_float4(o[0], o[1], o[2], o[3]);
            }
        }
    } else {   // CONV: g_h = z ; g_acc = z * dis^2
        float dd = valid ? g_dis[grow] : 0.f;
        float d2 = dd * dd;
        #pragma unroll
        for (int j0 = 0; j0 < 64; j0 += 4) {
            float4 v = *(const float4*)&srow[j0];
            if (valid) {
                *(float4*)&g_h[(size_t)grow * D + cb + j0] = v;
                *(float4*)&g_acc[(size_t)grow * D + cb + j0] =
                    make_float4(v.x * d2, v.y * d2, v.z * d2, v.w * d2);
            }
        }
    }
}

// ---------------- edge scatter: acc[dst] += h[src] * dis[src]*dis[dst] ----------------
__global__ void __launch_bounds__(256) k_scatter(const int* __restrict__ ei) {
    int e = blockIdx.x * 8 + (threadIdx.x >> 5);
    if (e >= Ee) return;
    int lane = threadIdx.x & 31;
    int s = ei[e], d = ei[Ee + e];
    float w = g_dis[s] * g_dis[d];
    const float4 v = *(const float4*)&g_h[(size_t)s * D + lane * 4];
    red4(&g_acc[(size_t)d * D + lane * 4], v.x * w, v.y * w, v.z * w, v.w * w);
}

// ---------------- host orchestration ----------------
extern "C" void kernel_launch(void* const* d_in, const int* in_sizes, int n_in,
                              void* d_out, int out_size)
{
    const float* node_feat = (const float*)d_in[0];
    const float* edge_feat = (const float*)d_in[1];
    const int*   ei        = (const int*)d_in[2];
    const float* enW1 = (const float*)d_in[3];  const float* enb1 = (const float*)d_in[4];
    const float* enW2 = (const float*)d_in[5];  const float* enb2 = (const float*)d_in[6];
    const float* enW3 = (const float*)d_in[7];  const float* enb3 = (const float*)d_in[8];
    const float* enlg = (const float*)d_in[9];  const float* enlb = (const float*)d_in[10];
    const float* eeW1 = (const float*)d_in[11]; const float* eeb1 = (const float*)d_in[12];
    const float* eeW2 = (const float*)d_in[13]; const float* eeb2 = (const float*)d_in[14];
    const float* eeW3 = (const float*)d_in[15]; const float* eeb3 = (const float*)d_in[16];
    const float* eelg = (const float*)d_in[17]; const float* eelb = (const float*)d_in[18];
    const float* procW = (const float*)d_in[19];
    const float* procb = (const float*)d_in[20];
    const float* bng   = (const float*)d_in[21];
    const float* bnb   = (const float*)d_in[22];
    const float* dW1 = (const float*)d_in[23]; const float* db1 = (const float*)d_in[24];
    const float* dW2 = (const float*)d_in[25]; const float* db2 = (const float*)d_in[26];
    const float* dW3 = (const float*)d_in[27]; const float* db3 = (const float*)d_in[28];
    const float* dlg = (const float*)d_in[29]; const float* dlb = (const float*)d_in[30];
    float* out = (float*)d_out;

    float* hn_ptr = nullptr; cudaGetSymbolAddress((void**)&hn_ptr, g_hn);
    float* y_ptr = nullptr;  cudaGetSymbolAddress((void**)&y_ptr, g_y);
    __nv_bfloat16 *bhi, *blo, *chi, *clo;
    cudaGetSymbolAddress((void**)&bhi, g_bhi);
    cudaGetSymbolAddress((void**)&blo, g_blo);
    cudaGetSymbolAddress((void**)&chi, g_chi);
    cudaGetSymbolAddress((void**)&clo, g_clo);

    cudaFuncSetAttribute(k_wgemm<0>, cudaFuncAttributeMaxDynamicSharedMemorySize, SMEM_MMA);
    cudaFuncSetAttribute(k_wgemm<1>, cudaFuncAttributeMaxDynamicSharedMemorySize, SMEM_MMA);
    cudaFuncSetAttribute(k_wgemm<2>, cudaFuncAttributeMaxDynamicSharedMemorySize, SMEM_MMA);
    cudaFuncSetAttribute(k_wgemm<3>, cudaFuncAttributeMaxDynamicSharedMemorySize, SMEM_MMA);

    auto lin1_smem = [](int kin) {
        int kinp = (kin + 3) & ~3;
        return (kinp * D + D + 64 * kinp) * (int)sizeof(float);
    };
    int sm_n = lin1_smem(NODE_IN);
    int sm_e = lin1_smem(EDGE_IN);

    // weight split slots:
    // 0: enW2  1: enW3  2: eeW2  3: eeW3  4+2s: proc s conv0  5+2s: conv1
    // 14: dW1  15: dW2  16: dW3
    k_wsplit<<<64, 256>>>(enW2, 0);
    k_wsplit<<<64, 256>>>(enW3, 1);
    k_wsplit<<<64, 256>>>(eeW2, 2);
    k_wsplit<<<64, 256>>>(eeW3, 3);
    for (int s = 0; s < STEPS; s++) {
        k_wsplit<<<64, 256>>>(procW + (size_t)(s * 2 + 0) * D * D, 4 + 2 * s);
        k_wsplit<<<64, 256>>>(procW + (size_t)(s * 2 + 1) * D * D, 5 + 2 * s);
    }
    k_wsplit<<<64, 256>>>(dW1, 14);
    k_wsplit<<<64, 256>>>(dW2, 15);
    k_wsplit<<<64, 256>>>(dW3, 16);

    // init + degrees
    k_zero<<<512, 256>>>();
    k_count<<<(Ee + 255) / 256, 256>>>(ei);
    k_dis<<<(Nn + 255) / 256, 256>>>();

    int NnT = (Nn + 127) / 128, EeT = Ee / 128;

    // node encoder
    k_lin1<NODE_IN><<<(Nn + 63) / 64, 256, sm_n>>>(node_feat, enW1, enb1, bhi, blo, Nn);
    k_wgemm<0><<<NnT, 256, SMEM_MMA>>>(bhi, blo, 0, enb2, nullptr, nullptr,
                                       nullptr, chi, clo, nullptr, Nn);
    k_wgemm<1><<<NnT, 256, SMEM_MMA>>>(chi, clo, 1, enb3, enlg, enlb,
                                       hn_ptr, nullptr, nullptr, nullptr, Nn);

    // edge encoder -> scatter-mean into g_acc
    k_lin1<EDGE_IN><<<(Ee + 63) / 64, 256, sm_e>>>(edge_feat, eeW1, eeb1, bhi, blo, Ee);
    k_wgemm<0><<<EeT, 256, SMEM_MMA>>>(bhi, blo, 2, eeb2, nullptr, nullptr,
                                       nullptr, chi, clo, nullptr, Ee);
    k_wgemm<2><<<EeT, 256, SMEM_MMA>>>(chi, clo, 3, eeb3, eelg, eelb,
                                       nullptr, nullptr, nullptr, ei, Ee);
    k_mix<<<(Nn * D + 255) / 256, 256>>>();

    // processor steps
    for (int s = 0; s < STEPS; s++) {
        const float* b0 = procb + (size_t)(s * 2 + 0) * D;
        const float* b1 = procb + (size_t)(s * 2 + 1) * D;

        k_split<<<(Nn * D + 255) / 256, 256>>>(hn_ptr, bhi, blo, Nn * D);
        k_wgemm<3><<<NnT, 256, SMEM_MMA>>>(bhi, blo, 4 + 2 * s, nullptr, nullptr, nullptr,
                                           nullptr, nullptr, nullptr, nullptr, Nn);
        k_scatter<<<(Ee + 7) / 8, 256>>>(ei);
        k_bnzero<<<1, 128>>>();
        k_post1<<<512, 128>>>(b0);
        k_bnfin<<<1, 128>>>(bng + (size_t)s * D, bnb + (size_t)s * D);

        k_split_bn<<<(Nn * D + 255) / 256, 256>>>(y_ptr, bhi, blo, Nn * D);
        k_wgemm<3><<<NnT, 256, SMEM_MMA>>>(bhi, blo, 5 + 2 * s, nullptr, nullptr, nullptr,
                                           nullptr, nullptr, nullptr, nullptr, Nn);
        k_scatter<<<(Ee + 7) / 8, 256>>>(ei);
        k_resid<<<(Nn * D + 255) / 256, 256>>>(b1);
    }

    // decoder
    k_split<<<(Nn * D + 255) / 256, 256>>>(hn_ptr, bhi, blo, Nn * D);
    k_wgemm<0><<<NnT, 256, SMEM_MMA>>>(bhi, blo, 14, db1, nullptr, nullptr,
                                       nullptr, chi, clo, nullptr, Nn);
    k_wgemm<0><<<NnT, 256, SMEM_MMA>>>(chi, clo, 15, db2, nullptr, nullptr,
                                       nullptr, bhi, blo, nullptr, Nn);
    k_wgemm<1><<<NnT, 256, SMEM_MMA>>>(bhi, blo, 16, db3, dlg, dlb,
                                       out, nullptr, nullptr, nullptr, Nn);
}

// round 5
// speedup vs baseline: 1.5307x; 1.2155x over previous
#include <cuda_runtime.h>
#include <cuda_bf16.h>
#include <mma.h>
#include <cstddef>
#include <cstdint>

using namespace nvcuda;

#define Nn 50000
#define Ee 800000
#define D 128
#define NODE_IN 19
#define EDGE_IN 4
#define STEPS 5
#define EPSf 1e-5f

typedef unsigned long long u64;
typedef unsigned int u32;

// ---------------- device scratch ----------------
__device__ float g_hn[Nn * D];
__device__ float g_acc[Nn * D];
__device__ float g_h[Nn * D];
__device__ float g_y[Nn * D];
__device__ float g_cnt[Nn];
__device__ float g_dis[Nn];
__device__ float g_bnsum[D];
__device__ float g_bnsq[D];
__device__ float g_bnscale[D];
__device__ float g_bnshift[D];

// split+transposed weights [slot][n][k], 17 slots
#define NSLOT 17
__device__ __nv_bfloat16 g_whi[NSLOT * D * D];
__device__ __nv_bfloat16 g_wlo[NSLOT * D * D];

__device__ __forceinline__ float leaky(float v) { return v > 0.f ? v : 0.05f * v; }

__device__ __forceinline__ void red4(float* p, float a, float b, float c, float d) {
    asm volatile("red.global.add.v4.f32 [%0], {%1,%2,%3,%4};"
                 :: "l"(p), "f"(a), "f"(b), "f"(c), "f"(d) : "memory");
}
__device__ __forceinline__ u32 bfpack(__nv_bfloat16 a, __nv_bfloat16 b) {
    __nv_bfloat162 t = __halves2bfloat162(a, b);
    return *(u32*)&t;
}

// ---------------- utility kernels ----------------
__global__ void k_zero() {
    int i = blockIdx.x * blockDim.x + threadIdx.x;
    int stride = gridDim.x * blockDim.x;
    for (int j = i; j < Nn * D; j += stride) g_acc[j] = 0.f;
    for (int j = i; j < Nn; j += stride) { g_cnt[j] = 0.f; g_dis[j] = 0.f; }
}

__global__ void k_count(const int* __restrict__ ei) {
    int e = blockIdx.x * blockDim.x + threadIdx.x;
    if (e >= Ee) return;
    atomicAdd(&g_cnt[ei[e]], 1.f);
    atomicAdd(&g_dis[ei[Ee + e]], 1.f);
}

__global__ void k_dis() {
    int i = blockIdx.x * blockDim.x + threadIdx.x;
    if (i < Nn) g_dis[i] = rsqrtf(g_dis[i] + 1.0f);
}

__global__ void k_mix() {
    int i = blockIdx.x * blockDim.x + threadIdx.x;
    if (i < Nn * D) g_hn[i] += g_acc[i] / fmaxf(g_cnt[i >> 7], 1.f);
}

__global__ void k_bnzero() {
    int c = threadIdx.x;
    if (c < D) { g_bnsum[c] = 0.f; g_bnsq[c] = 0.f; }
}

__global__ void k_post1(const float* __restrict__ bias) {
    int c = threadIdx.x;
    float b = bias[c];
    float s = 0.f, q = 0.f;
    for (int row = blockIdx.x; row < Nn; row += gridDim.x) {
        float v = g_acc[(size_t)row * D + c] + b;
        v = leaky(v);
        g_y[(size_t)row * D + c] = v;
        s += v; q += v * v;
    }
    atomicAdd(&g_bnsum[c], s);
    atomicAdd(&g_bnsq[c], q);
}

__global__ void k_bnfin(const float* __restrict__ g, const float* __restrict__ b) {
    int c = threadIdx.x;
    if (c < D) {
        float m = g_bnsum[c] * (1.f / (float)Nn);
        float v = g_bnsq[c] * (1.f / (float)Nn) - m * m;
        float sc = g[c] * rsqrtf(v + EPSf);
        g_bnscale[c] = sc;
        g_bnshift[c] = b[c] - m * sc;
    }
}

__global__ void k_resid(const float* __restrict__ bias) {
    int i = blockIdx.x * blockDim.x + threadIdx.x;
    if (i < Nn * D) g_hn[i] += g_acc[i] + bias[i & (D - 1)];
}

// all 17 weight splits in one launch: grid (64, 17)
__global__ void k_wsplit_all(
    const float* __restrict__ enW2, const float* __restrict__ enW3,
    const float* __restrict__ eeW2, const float* __restrict__ eeW3,
    const float* __restrict__ procW,
    const float* __restrict__ dW1, const float* __restrict__ dW2,
    const float* __restrict__ dW3)
{
    int slot = blockIdx.y;
    const float* W;
    if (slot == 0) W = enW2;
    else if (slot == 1) W = enW3;
    else if (slot == 2) W = eeW2;
    else if (slot == 3) W = eeW3;
    else if (slot < 14) W = procW + (size_t)(slot - 4) * D * D;
    else if (slot == 14) W = dW1;
    else if (slot == 15) W = dW2;
    else W = dW3;
    int i = blockIdx.x * 256 + threadIdx.x;
    int k = i >> 7, n = i & 127;
    float v = W[i];
    __nv_bfloat16 h = __float2bfloat16(v);
    g_whi[slot * D * D + n * D + k] = h;
    g_wlo[slot * D * D + n * D + k] = __float2bfloat16(v - __bfloat162float(h));
}

// ---------------- fused MLP kernel ----------------
// smem (bytes):
#define LDA 136                     // bf16 elems per row (stride 272B)
#define LDS_F 136
#define OFF_AH 0                    // 34816
#define OFF_AL 34816
#define OFF_WH 69632                // 34816
#define OFF_WL 104448
#define OFF_STG 69632               // fp32 stage, aliases W (69632 B)
#define OFF_CST 139264              // [0,512) bias_cur | [512,1024) lng | [1024,1536) lnb | [1536,2048) bias1
#define OFF_IN 141824               // scalar-L1 input tile, up to 10240 B
#define SMEM_F 152064

// EPI: 0 = LN -> out fp32; 1 = LN -> red4 scatter g_acc[esrc]; 2 = conv (g_h, g_acc=h*dis^2)
// KIN > 0: scalar first layer [M,KIN] @ W1 + bias1, leaky, split
// KIN == 0: fp32 input [M,128], optional BN affine, split
template <int KIN, int NL, int EPI, bool BN>
__global__ void __launch_bounds__(256, 1) k_fused(
    const float* __restrict__ in,
    int slot0, int slot1, int slot2,
    const float* __restrict__ wb0, const float* __restrict__ wb1, const float* __restrict__ wb2,
    const float* __restrict__ W1, const float* __restrict__ bias1,
    const float* __restrict__ lng, const float* __restrict__ lnb,
    float* __restrict__ out, const int* __restrict__ esrc, int M)
{
    constexpr int KINP = (KIN + 3) & ~3;
    extern __shared__ char smem[];
    int tid = threadIdx.x, wid = tid >> 5;
    int tb = blockIdx.x * 128;

    __nv_bfloat16* Ah = (__nv_bfloat16*)(smem + OFF_AH);
    __nv_bfloat16* Al = (__nv_bfloat16*)(smem + OFF_AL);
    __nv_bfloat16* Wh = (__nv_bfloat16*)(smem + OFF_WH);
    __nv_bfloat16* Wl = (__nv_bfloat16*)(smem + OFF_WL);
    float* stg  = (float*)(smem + OFF_STG);
    float* cstb = (float*)(smem + OFF_CST);
    float* cstg = (float*)(smem + OFF_CST + 512);
    float* cstl = (float*)(smem + OFF_CST + 1024);
    float* cst1 = (float*)(smem + OFF_CST + 1536);

    int r = tid >> 1, half = tid & 1, cb = half * 64;
    int grow = tb + r;
    bool valid = grow < M;

    if (EPI != 2 && tid < D) { cstg[tid] = lng[tid]; cstl[tid] = lnb[tid]; }

    // ============ build initial A (bf16 hi/lo in smem) ============
    if (KIN > 0) {
        float* W1s = (float*)(smem + OFF_WH);         // KINP*128 fp32 (<= 10240 B)
        float* cin = (float*)(smem + OFF_IN);         // 128*KINP fp32
        for (int i = tid; i < KINP * D; i += 256)
            W1s[i] = (i < KIN * D) ? W1[i] : 0.f;
        if (tid < D) cst1[tid] = bias1[tid];
        for (int i = tid; i < 128 * KINP; i += 256) {
            int row = i / KINP, k = i % KINP;
            int gr = min(tb + row, M - 1);
            cin[i] = (k < KIN) ? in[(size_t)gr * KIN + k] : 0.f;
        }
        __syncthreads();

        float acc[64];
        #pragma unroll
        for (int j = 0; j < 64; j++) acc[j] = cst1[cb + j];
        for (int k = 0; k < KIN; k++) {
            float xv = cin[r * KINP + k];
            const float* wrow = &W1s[k * D + cb];
            #pragma unroll
            for (int j = 0; j < 64; j++) acc[j] = fmaf(xv, wrow[j], acc[j]);
        }
        __syncthreads();   // done reading W1s/cin before Wh overwrite
        #pragma unroll
        for (int j0 = 0; j0 < 64; j0 += 8) {
            u32 hi[4], lo[4];
            #pragma unroll
            for (int jj = 0; jj < 8; jj += 2) {
                float z0 = leaky(acc[j0 + jj]);
                float z1 = leaky(acc[j0 + jj + 1]);
                __nv_bfloat16 h0 = __float2bfloat16(z0), h1 = __float2bfloat16(z1);
                hi[jj >> 1] = bfpack(h0, h1);
                lo[jj >> 1] = bfpack(__float2bfloat16(z0 - __bfloat162float(h0)),
                                     __float2bfloat16(z1 - __bfloat162float(h1)));
            }
            *(uint4*)&Ah[r * LDA + cb + j0] = make_uint4(hi[0], hi[1], hi[2], hi[3]);
            *(uint4*)&Al[r * LDA + cb + j0] = make_uint4(lo[0], lo[1], lo[2], lo[3]);
        }
    } else {
        float bnsc[1], bnsh[1];  // dummies to quiet compiler in non-BN path
        (void)bnsc; (void)bnsh;
        for (int idx = tid; idx < 4096; idx += 256) {
            int row = idx >> 5, c4 = idx & 31;
            int gr = min(tb + row, M - 1);
            float4 v = ((const float4*)in)[(size_t)gr * 32 + c4];
            if (BN) {
                int c = c4 * 4;
                v.x = fmaf(v.x, g_bnscale[c],     g_bnshift[c]);
                v.y = fmaf(v.y, g_bnscale[c + 1], g_bnshift[c + 1]);
                v.z = fmaf(v.z, g_bnscale[c + 2], g_bnshift[c + 2]);
                v.w = fmaf(v.w, g_bnscale[c + 3], g_bnshift[c + 3]);
            }
            __nv_bfloat16 h0 = __float2bfloat16(v.x), h1 = __float2bfloat16(v.y);
            __nv_bfloat16 h2 = __float2bfloat16(v.z), h3 = __float2bfloat16(v.w);
            u32 hi01 = bfpack(h0, h1), hi23 = bfpack(h2, h3);
            u32 lo01 = bfpack(__float2bfloat16(v.x - __bfloat162float(h0)),
                              __float2bfloat16(v.y - __bfloat162float(h1)));
            u32 lo23 = bfpack(__float2bfloat16(v.z - __bfloat162float(h2)),
                              __float2bfloat16(v.w - __bfloat162float(h3)));
            *(uint2*)&Ah[row * LDA + c4 * 4] = make_uint2(hi01, hi23);
            *(uint2*)&Al[row * LDA + c4 * 4] = make_uint2(lo01, lo23);
        }
    }
    __syncthreads();

    // ============ WMMA layers ============
    int slots[3] = {slot0, slot1, slot2};
    const float* wbs[3] = {wb0, wb1, wb2};
    int wr = wid & 3, wc = wid >> 2;

    #pragma unroll
    for (int l = 0; l < NL; l++) {
        // load split weights for this layer (overwrites stage of prev layer)
        const uint4* pwh = ((const uint4*)g_whi) + (size_t)slots[l] * 2048;
        const uint4* pwl = ((const uint4*)g_wlo) + (size_t)slots[l] * 2048;
        for (int i = tid; i < 2048; i += 256) {
            int row = i >> 4, c = i & 15;
            *(uint4*)&Wh[row * LDA + c * 8] = pwh[row * 16 + c];
            *(uint4*)&Wl[row * LDA + c * 8] = pwl[row * 16 + c];
        }
        if (EPI != 2 && tid < D) cstb[tid] = wbs[l][tid];
        __syncthreads();

        wmma::fragment<wmma::accumulator, 16, 16, 16, float> acc[2][4];
        #pragma unroll
        for (int i = 0; i < 2; i++)
            #pragma unroll
            for (int j = 0; j < 4; j++) wmma::fill_fragment(acc[i][j], 0.f);

        const __nv_bfloat16* Ap[3] = {Ah, Ah, Al};
        const __nv_bfloat16* Wp[3] = {Wh, Wl, Wh};
        #pragma unroll
        for (int p = 0; p < 3; p++) {
            const __nv_bfloat16* A = Ap[p];
            const __nv_bfloat16* W = Wp[p];
            #pragma unroll
            for (int k = 0; k < 8; k++) {
                wmma::fragment<wmma::matrix_a, 16, 16, 16, __nv_bfloat16, wmma::row_major> af[2];
                wmma::fragment<wmma::matrix_b, 16, 16, 16, __nv_bfloat16, wmma::col_major> bfr[4];
                wmma::load_matrix_sync(af[0], &A[(wr * 32) * LDA + k * 16], LDA);
                wmma::load_matrix_sync(af[1], &A[(wr * 32 + 16) * LDA + k * 16], LDA);
                #pragma unroll
                for (int j = 0; j < 4; j++)
                    wmma::load_matrix_sync(bfr[j], &W[(wc * 64 + j * 16) * LDA + k * 16], LDA);
                #pragma unroll
                for (int i = 0; i < 2; i++)
                    #pragma unroll
                    for (int j = 0; j < 4; j++)
                        wmma::mma_sync(acc[i][j], af[i], bfr[j], acc[i][j]);
            }
        }
        __syncthreads();   // all W reads done; stage may overwrite W region
        #pragma unroll
        for (int i = 0; i < 2; i++)
            #pragma unroll
            for (int j = 0; j < 4; j++)
                wmma::store_matrix_sync(&stg[(wr * 32 + i * 16) * LDS_F + wc * 64 + j * 16],
                                        acc[i][j], LDS_F, wmma::mem_row_major);
        __syncthreads();

        const float* srow = &stg[r * LDS_F + cb];

        if (l < NL - 1) {
            // hidden epilogue: bias + leaky -> re-split into A
            #pragma unroll
            for (int j0 = 0; j0 < 64; j0 += 8) {
                u32 hi[4], lo[4];
                #pragma unroll
                for (int jj = 0; jj < 8; jj += 2) {
                    int c = cb + j0 + jj;
                    float z0 = leaky(srow[j0 + jj] + cstb[c]);
                    float z1 = leaky(srow[j0 + jj + 1] + cstb[c + 1]);
                    __nv_bfloat16 h0 = __float2bfloat16(z0), h1 = __float2bfloat16(z1);
                    hi[jj >> 1] = bfpack(h0, h1);
                    lo[jj >> 1] = bfpack(__float2bfloat16(z0 - __bfloat162float(h0)),
                                         __float2bfloat16(z1 - __bfloat162float(h1)));
                }
                *(uint4*)&Ah[r * LDA + cb + j0] = make_uint4(hi[0], hi[1], hi[2], hi[3]);
                *(uint4*)&Al[r * LDA + cb + j0] = make_uint4(lo[0], lo[1], lo[2], lo[3]);
            }
        } else if (EPI == 0 || EPI == 1) {
            // final: bias + LayerNorm (-> out or scatter)
            float s = 0.f, q = 0.f;
            #pragma unroll
            for (int j = 0; j < 64; j++) {
                float z = srow[j] + cstb[cb + j];
                s += z; q += z * z;
            }
            s += __shfl_xor_sync(0xffffffffu, s, 1);
            q += __shfl_xor_sync(0xffffffffu, q, 1);
            float m = s * (1.f / (float)D);
            float var = q * (1.f / (float)D) - m * m;
            float inv = rsqrtf(var + EPSf);
            int sidx = (EPI == 1 && valid) ? esrc[grow] : 0;
            #pragma unroll
            for (int j0 = 0; j0 < 64; j0 += 4) {
                float o[4];
                #pragma unroll
                for (int jj = 0; jj < 4; jj++) {
                    int c = cb + j0 + jj;
                    float z = srow[j0 + jj] + cstb[c];
                    o[jj] = (z - m) * inv * cstg[c] + cstl[c];
                }
                if (EPI == 1) {
                    if (valid)
                        red4(&g_acc[(size_t)sidx * D + cb + j0], o[0], o[1], o[2], o[3]);
                } else if (valid) {
                    *(float4*)&out[(size_t)grow * D + cb + j0] = make_float4(o[0], o[1], o[2], o[3]);
                }
            }
        } else {
            // conv: g_h = z ; g_acc = z * dis^2 (no bias)
            float dd = valid ? g_dis[grow] : 0.f;
            float d2 = dd * dd;
            #pragma unroll
            for (int j0 = 0; j0 < 64; j0 += 4) {
                float4 v = *(const float4*)&srow[j0];
                if (valid) {
                    *(float4*)&g_h[(size_t)grow * D + cb + j0] = v;
                    *(float4*)&g_acc[(size_t)grow * D + cb + j0] =
                        make_float4(v.x * d2, v.y * d2, v.z * d2, v.w * d2);
                }
            }
        }
        __syncthreads();
    }
}

// ---------------- edge scatter: acc[dst] += h[src] * dis[src]*dis[dst] ----------------
__global__ void __launch_bounds__(256) k_scatter(const int* __restrict__ ei) {
    int e = blockIdx.x * 8 + (threadIdx.x >> 5);
    if (e >= Ee) return;
    int lane = threadIdx.x & 31;
    int s = ei[e], d = ei[Ee + e];
    float w = g_dis[s] * g_dis[d];
    const float4 v = *(const float4*)&g_h[(size_t)s * D + lane * 4];
    red4(&g_acc[(size_t)d * D + lane * 4], v.x * w, v.y * w, v.z * w, v.w * w);
}

// ---------------- host orchestration ----------------
extern "C" void kernel_launch(void* const* d_in, const int* in_sizes, int n_in,
                              void* d_out, int out_size)
{
    const float* node_feat = (const float*)d_in[0];
    const float* edge_feat = (const float*)d_in[1];
    const int*   ei        = (const int*)d_in[2];
    const float* enW1 = (const float*)d_in[3];  const float* enb1 = (const float*)d_in[4];
    const float* enW2 = (const float*)d_in[5];  const float* enb2 = (const float*)d_in[6];
    const float* enW3 = (const float*)d_in[7];  const float* enb3 = (const float*)d_in[8];
    const float* enlg = (const float*)d_in[9];  const float* enlb = (const float*)d_in[10];
    const float* eeW1 = (const float*)d_in[11]; const float* eeb1 = (const float*)d_in[12];
    const float* eeW2 = (const float*)d_in[13]; const float* eeb2 = (const float*)d_in[14];
    const float* eeW3 = (const float*)d_in[15]; const float* eeb3 = (const float*)d_in[16];
    const float* eelg = (const float*)d_in[17]; const float* eelb = (const float*)d_in[18];
    const float* procW = (const float*)d_in[19];
    const float* procb = (const float*)d_in[20];
    const float* bng   = (const float*)d_in[21];
    const float* bnb   = (const float*)d_in[22];
    const float* dW1 = (const float*)d_in[23]; const float* db1 = (const float*)d_in[24];
    const float* dW2 = (const float*)d_in[25]; const float* db2 = (const float*)d_in[26];
    const float* dW3 = (const float*)d_in[27]; const float* db3 = (const float*)d_in[28];
    const float* dlg = (const float*)d_in[29]; const float* dlb = (const float*)d_in[30];
    float* out = (float*)d_out;

    float* hn_ptr = nullptr; cudaGetSymbolAddress((void**)&hn_ptr, g_hn);
    float* y_ptr = nullptr;  cudaGetSymbolAddress((void**)&y_ptr, g_y);

    cudaFuncSetAttribute(k_fused<NODE_IN, 2, 0, false>, cudaFuncAttributeMaxDynamicSharedMemorySize, SMEM_F);
    cudaFuncSetAttribute(k_fused<EDGE_IN, 2, 1, false>, cudaFuncAttributeMaxDynamicSharedMemorySize, SMEM_F);
    cudaFuncSetAttribute(k_fused<0, 1, 2, false>, cudaFuncAttributeMaxDynamicSharedMemorySize, SMEM_F);
    cudaFuncSetAttribute(k_fused<0, 1, 2, true>,  cudaFuncAttributeMaxDynamicSharedMemorySize, SMEM_F);
    cudaFuncSetAttribute(k_fused<0, 3, 0, false>, cudaFuncAttributeMaxDynamicSharedMemorySize, SMEM_F);

    int NnT = (Nn + 127) / 128, EeT = Ee / 128;

    // 1: all weight splits
    k_wsplit_all<<<dim3(64, NSLOT), 256>>>(enW2, enW3, eeW2, eeW3, procW, dW1, dW2, dW3);
    // 2-4: init + degrees
    k_zero<<<512, 256>>>();
    k_count<<<(Ee + 255) / 256, 256>>>(ei);
    k_dis<<<(Nn + 255) / 256, 256>>>();

    // 5: node encoder (fused)
    k_fused<NODE_IN, 2, 0, false><<<NnT, 256, SMEM_F>>>(
        node_feat, 0, 1, 0, enb2, enb3, nullptr, enW1, enb1, enlg, enlb,
        hn_ptr, nullptr, Nn);
    // 6: edge encoder (fused, scatter-mean into g_acc)  <-- profiled launch
    k_fused<EDGE_IN, 2, 1, false><<<EeT, 256, SMEM_F>>>(
        edge_feat, 2, 3, 0, eeb2, eeb3, nullptr, eeW1, eeb1, eelg, eelb,
        nullptr, ei, Ee);
    // 7: mix
    k_mix<<<(Nn * D + 255) / 256, 256>>>();

    // processor steps
    for (int s = 0; s < STEPS; s++) {
        const float* b0 = procb + (size_t)(s * 2 + 0) * D;
        const float* b1 = procb + (size_t)(s * 2 + 1) * D;

        k_fused<0, 1, 2, false><<<NnT, 256, SMEM_F>>>(
            hn_ptr, 4 + 2 * s, 0, 0, nullptr, nullptr, nullptr,
            nullptr, nullptr, nullptr, nullptr, nullptr, nullptr, Nn);
        k_scatter<<<(Ee + 7) / 8, 256>>>(ei);
        k_bnzero<<<1, 128>>>();
        k_post1<<<512, 128>>>(b0);
        k_bnfin<<<1, 128>>>(bng + (size_t)s * D, bnb + (size_t)s * D);

        k_fused<0, 1, 2, true><<<NnT, 256, SMEM_F>>>(
            y_ptr, 5 + 2 * s, 0, 0, nullptr, nullptr, nullptr,
            nullptr, nullptr, nullptr, nullptr, nullptr, nullptr, Nn);
        k_scatter<<<(Ee + 7) / 8, 256>>>(ei);
        k_resid<<<(Nn * D + 255) / 256, 256>>>(b1);
    }

    // decoder (fused 3 layers + LN)
    k_fused<0, 3, 0, false><<<NnT, 256, SMEM_F>>>(
        hn_ptr, 14, 15, 16, db1, db2, db3,
        nullptr, nullptr, dlg, dlb, out, nullptr, Nn);
}

// round 6
// speedup vs baseline: 2.0042x; 1.3093x over previous
#include <cuda_runtime.h>
#include <cuda_bf16.h>
#include <mma.h>
#include <cstddef>
#include <cstdint>

using namespace nvcuda;

#define Nn 50000
#define Ee 800000
#define D 128
#define NODE_IN 19
#define EDGE_IN 4
#define STEPS 5
#define EPSf 1e-5f

typedef unsigned long long u64;
typedef unsigned int u32;

// ---------------- device scratch ----------------
__device__ float g_hn[Nn * D];
__device__ float g_acc[Nn * D];    // edge-encoder scatter-mean accumulator
__device__ float g_h[Nn * D];      // conv GEMM output
__device__ float g_y[Nn * D];      // post conv1 activations
__device__ float g_cnt[Nn];        // src edge counts (scatter-mean denom)
__device__ float g_dis[Nn];        // deg^{-1/2}
__device__ int   g_degi[Nn];       // dst degree (int)
__device__ int   g_fill[Nn];       // CSR fill cursors
__device__ int   g_rowoff[Nn + 1]; // CSR row offsets (by dst)
__device__ int   g_csrs[Ee];       // CSR src indices
__device__ float g_csrw[Ee];       // CSR edge weights dis[s]*dis[d]
__device__ float g_bnsum[D];
__device__ float g_bnsq[D];
__device__ float g_bnscale[D];
__device__ float g_bnshift[D];

// split+transposed weights [slot][n][k], 17 slots
#define NSLOT 17
__device__ __nv_bfloat16 g_whi[NSLOT * D * D];
__device__ __nv_bfloat16 g_wlo[NSLOT * D * D];

__device__ __forceinline__ float leaky(float v) { return v > 0.f ? v : 0.05f * v; }

__device__ __forceinline__ void red4(float* p, float a, float b, float c, float d) {
    asm volatile("red.global.add.v4.f32 [%0], {%1,%2,%3,%4};"
                 :: "l"(p), "f"(a), "f"(b), "f"(c), "f"(d) : "memory");
}
__device__ __forceinline__ u32 bfpack(__nv_bfloat16 a, __nv_bfloat16 b) {
    __nv_bfloat162 t = __halves2bfloat162(a, b);
    return *(u32*)&t;
}

// ---------------- utility kernels ----------------
__global__ void k_zero() {
    int i = blockIdx.x * blockDim.x + threadIdx.x;
    int stride = gridDim.x * blockDim.x;
    for (int j = i; j < Nn * D; j += stride) g_acc[j] = 0.f;
    for (int j = i; j < Nn; j += stride) {
        g_cnt[j] = 0.f; g_degi[j] = 0; g_fill[j] = 0;
    }
}

__global__ void k_count(const int* __restrict__ ei) {
    int e = blockIdx.x * blockDim.x + threadIdx.x;
    if (e >= Ee) return;
    atomicAdd(&g_cnt[ei[e]], 1.f);
    atomicAdd(&g_degi[ei[Ee + e]], 1);
}

// single-block exclusive scan over g_degi -> g_rowoff
__global__ void k_scan() {
    __shared__ int ts[1024];
    int t = threadIdx.x;
    const int CH = (Nn + 1023) / 1024;   // 49
    int start = t * CH;
    int end = min(start + CH, Nn);
    int sum = 0;
    for (int i = start; i < end; i++) sum += g_degi[i];
    ts[t] = sum;
    __syncthreads();
    for (int off = 1; off < 1024; off <<= 1) {
        int v = (t >= off) ? ts[t - off] : 0;
        __syncthreads();
        ts[t] += v;
        __syncthreads();
    }
    int run = (t == 0) ? 0 : ts[t - 1];
    for (int i = start; i < end; i++) { g_rowoff[i] = run; run += g_degi[i]; }
    if (t == 1023) g_rowoff[Nn] = run;
}

__global__ void k_dis() {
    int i = blockIdx.x * blockDim.x + threadIdx.x;
    if (i < Nn) g_dis[i] = rsqrtf((float)g_degi[i] + 1.0f);
}

__global__ void k_fill(const int* __restrict__ ei) {
    int e = blockIdx.x * blockDim.x + threadIdx.x;
    if (e >= Ee) return;
    int s = ei[e], d = ei[Ee + e];
    int pos = g_rowoff[d] + atomicAdd(&g_fill[d], 1);
    g_csrs[pos] = s;
    g_csrw[pos] = g_dis[s] * g_dis[d];
}

__global__ void k_mix() {
    int i = blockIdx.x * blockDim.x + threadIdx.x;
    if (i < Nn * D) g_hn[i] += g_acc[i] / fmaxf(g_cnt[i >> 7], 1.f);
}

__global__ void k_bnzero() {
    int c = threadIdx.x;
    if (c < D) { g_bnsum[c] = 0.f; g_bnsq[c] = 0.f; }
}

__global__ void k_bnfin(const float* __restrict__ g, const float* __restrict__ b) {
    int c = threadIdx.x;
    if (c < D) {
        float m = g_bnsum[c] * (1.f / (float)Nn);
        float v = g_bnsq[c] * (1.f / (float)Nn) - m * m;
        float sc = g[c] * rsqrtf(v + EPSf);
        g_bnscale[c] = sc;
        g_bnshift[c] = b[c] - m * sc;
    }
}

// ---------------- CSR gather kernels (warp per node) ----------------
// A: y = leaky(agg + b0); write g_y; accumulate BN stats
__global__ void __launch_bounds__(256) k_gatherA(const float* __restrict__ b0) {
    int lane = threadIdx.x & 31;
    int gw = blockIdx.x * 8 + (threadIdx.x >> 5);
    int nw = gridDim.x * 8;
    int c0 = lane * 4;
    float4 bb = *(const float4*)&b0[c0];
    float s0 = 0.f, s1 = 0.f, s2 = 0.f, s3 = 0.f;
    float q0 = 0.f, q1 = 0.f, q2 = 0.f, q3 = 0.f;

    for (int node = gw; node < Nn; node += nw) {
        float dd = g_dis[node];
        float d2 = dd * dd;
        float4 a = *(const float4*)&g_h[(size_t)node * D + c0];
        a.x *= d2; a.y *= d2; a.z *= d2; a.w *= d2;
        int p = g_rowoff[node], p1 = g_rowoff[node + 1];
        for (; p + 1 < p1; p += 2) {
            int sA = g_csrs[p];     float wA = g_csrw[p];
            int sB = g_csrs[p + 1]; float wB = g_csrw[p + 1];
            float4 vA = *(const float4*)&g_h[(size_t)sA * D + c0];
            float4 vB = *(const float4*)&g_h[(size_t)sB * D + c0];
            a.x = fmaf(vA.x, wA, a.x); a.y = fmaf(vA.y, wA, a.y);
            a.z = fmaf(vA.z, wA, a.z); a.w = fmaf(vA.w, wA, a.w);
            a.x = fmaf(vB.x, wB, a.x); a.y = fmaf(vB.y, wB, a.y);
            a.z = fmaf(vB.z, wB, a.z); a.w = fmaf(vB.w, wB, a.w);
        }
        if (p < p1) {
            int sA = g_csrs[p]; float wA = g_csrw[p];
            float4 vA = *(const float4*)&g_h[(size_t)sA * D + c0];
            a.x = fmaf(vA.x, wA, a.x); a.y = fmaf(vA.y, wA, a.y);
            a.z = fmaf(vA.z, wA, a.z); a.w = fmaf(vA.w, wA, a.w);
        }
        float v0 = leaky(a.x + bb.x), v1 = leaky(a.y + bb.y);
        float v2 = leaky(a.z + bb.z), v3 = leaky(a.w + bb.w);
        *(float4*)&g_y[(size_t)node * D + c0] = make_float4(v0, v1, v2, v3);
        s0 += v0; s1 += v1; s2 += v2; s3 += v3;
        q0 += v0 * v0; q1 += v1 * v1; q2 += v2 * v2; q3 += v3 * v3;
    }
    red4(&g_bnsum[c0], s0, s1, s2, s3);
    red4(&g_bnsq[c0],  q0, q1, q2, q3);
}

// B: hn += agg + b1
__global__ void __launch_bounds__(256) k_gatherB(const float* __restrict__ b1) {
    int lane = threadIdx.x & 31;
    int gw = blockIdx.x * 8 + (threadIdx.x >> 5);
    int nw = gridDim.x * 8;
    int c0 = lane * 4;
    float4 bb = *(const float4*)&b1[c0];

    for (int node = gw; node < Nn; node += nw) {
        float dd = g_dis[node];
        float d2 = dd * dd;
        float4 a = *(const float4*)&g_h[(size_t)node * D + c0];
        a.x *= d2; a.y *= d2; a.z *= d2; a.w *= d2;
        int p = g_rowoff[node], p1 = g_rowoff[node + 1];
        for (; p + 1 < p1; p += 2) {
            int sA = g_csrs[p];     float wA = g_csrw[p];
            int sB = g_csrs[p + 1]; float wB = g_csrw[p + 1];
            float4 vA = *(const float4*)&g_h[(size_t)sA * D + c0];
            float4 vB = *(const float4*)&g_h[(size_t)sB * D + c0];
            a.x = fmaf(vA.x, wA, a.x); a.y = fmaf(vA.y, wA, a.y);
            a.z = fmaf(vA.z, wA, a.z); a.w = fmaf(vA.w, wA, a.w);
            a.x = fmaf(vB.x, wB, a.x); a.y = fmaf(vB.y, wB, a.y);
            a.z = fmaf(vB.z, wB, a.z); a.w = fmaf(vB.w, wB, a.w);
        }
        if (p < p1) {
            int sA = g_csrs[p]; float wA = g_csrw[p];
            float4 vA = *(const float4*)&g_h[(size_t)sA * D + c0];
            a.x = fmaf(vA.x, wA, a.x); a.y = fmaf(vA.y, wA, a.y);
            a.z = fmaf(vA.z, wA, a.z); a.w = fmaf(vA.w, wA, a.w);
        }
        float4 h4 = *(const float4*)&g_hn[(size_t)node * D + c0];
        h4.x += a.x + bb.x; h4.y += a.y + bb.y;
        h4.z += a.z + bb.z; h4.w += a.w + bb.w;
        *(float4*)&g_hn[(size_t)node * D + c0] = h4;
    }
}

// all 17 weight splits in one launch: grid (64, 17)
__global__ void k_wsplit_all(
    const float* __restrict__ enW2, const float* __restrict__ enW3,
    const float* __restrict__ eeW2, const float* __restrict__ eeW3,
    const float* __restrict__ procW,
    const float* __restrict__ dW1, const float* __restrict__ dW2,
    const float* __restrict__ dW3)
{
    int slot = blockIdx.y;
    const float* W;
    if (slot == 0) W = enW2;
    else if (slot == 1) W = enW3;
    else if (slot == 2) W = eeW2;
    else if (slot == 3) W = eeW3;
    else if (slot < 14) W = procW + (size_t)(slot - 4) * D * D;
    else if (slot == 14) W = dW1;
    else if (slot == 15) W = dW2;
    else W = dW3;
    int i = blockIdx.x * 256 + threadIdx.x;
    int k = i >> 7, n = i & 127;
    float v = W[i];
    __nv_bfloat16 h = __float2bfloat16(v);
    g_whi[slot * D * D + n * D + k] = h;
    g_wlo[slot * D * D + n * D + k] = __float2bfloat16(v - __bfloat162float(h));
}

// ---------------- fused MLP kernel ----------------
#define LDA 136
#define LDS_F 136
#define OFF_AH 0
#define OFF_AL 34816
#define OFF_WH 69632
#define OFF_WL 104448
#define OFF_STG 69632               // fp32 stage aliases W
#define OFF_CST 139264
#define OFF_IN 141824
#define SMEM_F 152064

// EPI: 0 = LN -> out fp32; 1 = LN -> red4 scatter g_acc[esrc]; 2 = conv (g_h only)
template <int KIN, int NL, int EPI, bool BN>
__global__ void __launch_bounds__(256, 1) k_fused(
    const float* __restrict__ in,
    int slot0, int slot1, int slot2,
    const float* __restrict__ wb0, const float* __restrict__ wb1, const float* __restrict__ wb2,
    const float* __restrict__ W1, const float* __restrict__ bias1,
    const float* __restrict__ lng, const float* __restrict__ lnb,
    float* __restrict__ out, const int* __restrict__ esrc, int M)
{
    constexpr int KINP = (KIN + 3) & ~3;
    extern __shared__ char smem[];
    int tid = threadIdx.x, wid = tid >> 5;
    int tb = blockIdx.x * 128;

    __nv_bfloat16* Ah = (__nv_bfloat16*)(smem + OFF_AH);
    __nv_bfloat16* Al = (__nv_bfloat16*)(smem + OFF_AL);
    __nv_bfloat16* Wh = (__nv_bfloat16*)(smem + OFF_WH);
    __nv_bfloat16* Wl = (__nv_bfloat16*)(smem + OFF_WL);
    float* stg  = (float*)(smem + OFF_STG);
    float* cstb = (float*)(smem + OFF_CST);
    float* cstg = (float*)(smem + OFF_CST + 512);
    float* cstl = (float*)(smem + OFF_CST + 1024);
    float* cst1 = (float*)(smem + OFF_CST + 1536);

    int r = tid >> 1, half = tid & 1, cb = half * 64;
    int grow = tb + r;
    bool valid = grow < M;

    if (EPI != 2 && tid < D) { cstg[tid] = lng[tid]; cstl[tid] = lnb[tid]; }

    // ============ build initial A (bf16 hi/lo in smem) ============
    if (KIN > 0) {
        float* W1s = (float*)(smem + OFF_WH);
        float* cin = (float*)(smem + OFF_IN);
        for (int i = tid; i < KINP * D; i += 256)
            W1s[i] = (i < KIN * D) ? W1[i] : 0.f;
        if (tid < D) cst1[tid] = bias1[tid];
        for (int i = tid; i < 128 * KINP; i += 256) {
            int row = i / KINP, k = i % KINP;
            int gr = min(tb + row, M - 1);
            cin[i] = (k < KIN) ? in[(size_t)gr * KIN + k] : 0.f;
        }
        __syncthreads();

        float acc[64];
        #pragma unroll
        for (int j = 0; j < 64; j++) acc[j] = cst1[cb + j];
        for (int k = 0; k < KIN; k++) {
            float xv = cin[r * KINP + k];
            const float* wrow = &W1s[k * D + cb];
            #pragma unroll
            for (int j = 0; j < 64; j++) acc[j] = fmaf(xv, wrow[j], acc[j]);
        }
        __syncthreads();
        #pragma unroll
        for (int j0 = 0; j0 < 64; j0 += 8) {
            u32 hi[4], lo[4];
            #pragma unroll
            for (int jj = 0; jj < 8; jj += 2) {
                float z0 = leaky(acc[j0 + jj]);
                float z1 = leaky(acc[j0 + jj + 1]);
                __nv_bfloat16 h0 = __float2bfloat16(z0), h1 = __float2bfloat16(z1);
                hi[jj >> 1] = bfpack(h0, h1);
                lo[jj >> 1] = bfpack(__float2bfloat16(z0 - __bfloat162float(h0)),
                                     __float2bfloat16(z1 - __bfloat162float(h1)));
            }
            *(uint4*)&Ah[r * LDA + cb + j0] = make_uint4(hi[0], hi[1], hi[2], hi[3]);
            *(uint4*)&Al[r * LDA + cb + j0] = make_uint4(lo[0], lo[1], lo[2], lo[3]);
        }
    } else {
        for (int idx = tid; idx < 4096; idx += 256) {
            int row = idx >> 5, c4 = idx & 31;
            int gr = min(tb + row, M - 1);
            float4 v = ((const float4*)in)[(size_t)gr * 32 + c4];
            if (BN) {
                int c = c4 * 4;
                v.x = fmaf(v.x, g_bnscale[c],     g_bnshift[c]);
                v.y = fmaf(v.y, g_bnscale[c + 1], g_bnshift[c + 1]);
                v.z = fmaf(v.z, g_bnscale[c + 2], g_bnshift[c + 2]);
                v.w = fmaf(v.w, g_bnscale[c + 3], g_bnshift[c + 3]);
            }
            __nv_bfloat16 h0 = __float2bfloat16(v.x), h1 = __float2bfloat16(v.y);
            __nv_bfloat16 h2 = __float2bfloat16(v.z), h3 = __float2bfloat16(v.w);
            u32 hi01 = bfpack(h0, h1), hi23 = bfpack(h2, h3);
            u32 lo01 = bfpack(__float2bfloat16(v.x - __bfloat162float(h0)),
                              __float2bfloat16(v.y - __bfloat162float(h1)));
            u32 lo23 = bfpack(__float2bfloat16(v.z - __bfloat162float(h2)),
                              __float2bfloat16(v.w - __bfloat162float(h3)));
            *(uint2*)&Ah[row * LDA + c4 * 4] = make_uint2(hi01, hi23);
            *(uint2*)&Al[row * LDA + c4 * 4] = make_uint2(lo01, lo23);
        }
    }
    __syncthreads();

    // ============ WMMA layers ============
    int slots[3] = {slot0, slot1, slot2};
    const float* wbs[3] = {wb0, wb1, wb2};
    int wr = wid & 3, wc = wid >> 2;

    #pragma unroll
    for (int l = 0; l < NL; l++) {
        const uint4* pwh = ((const uint4*)g_whi) + (size_t)slots[l] * 2048;
        const uint4* pwl = ((const uint4*)g_wlo) + (size_t)slots[l] * 2048;
        for (int i = tid; i < 2048; i += 256) {
            int row = i >> 4, c = i & 15;
            *(uint4*)&Wh[row * LDA + c * 8] = pwh[row * 16 + c];
            *(uint4*)&Wl[row * LDA + c * 8] = pwl[row * 16 + c];
        }
        if (EPI != 2 && tid < D) cstb[tid] = wbs[l][tid];
        __syncthreads();

        wmma::fragment<wmma::accumulator, 16, 16, 16, float> acc[2][4];
        #pragma unroll
        for (int i = 0; i < 2; i++)
            #pragma unroll
            for (int j = 0; j < 4; j++) wmma::fill_fragment(acc[i][j], 0.f);

        const __nv_bfloat16* Ap[3] = {Ah, Ah, Al};
        const __nv_bfloat16* Wp[3] = {Wh, Wl, Wh};
        #pragma unroll
        for (int p = 0; p < 3; p++) {
            const __nv_bfloat16* A = Ap[p];
            const __nv_bfloat16* W = Wp[p];
            #pragma unroll
            for (int k = 0; k < 8; k++) {
                wmma::fragment<wmma::matrix_a, 16, 16, 16, __nv_bfloat16, wmma::row_major> af[2];
                wmma::fragment<wmma::matrix_b, 16, 16, 16, __nv_bfloat16, wmma::col_major> bfr[4];
                wmma::load_matrix_sync(af[0], &A[(wr * 32) * LDA + k * 16], LDA);
                wmma::load_matrix_sync(af[1], &A[(wr * 32 + 16) * LDA + k * 16], LDA);
                #pragma unroll
                for (int j = 0; j < 4; j++)
                    wmma::load_matrix_sync(bfr[j], &W[(wc * 64 + j * 16) * LDA + k * 16], LDA);
                #pragma unroll
                for (int i = 0; i < 2; i++)
                    #pragma unroll
                    for (int j = 0; j < 4; j++)
                        wmma::mma_sync(acc[i][j], af[i], bfr[j], acc[i][j]);
            }
        }
        __syncthreads();
        #pragma unroll
        for (int i = 0; i < 2; i++)
            #pragma unroll
            for (int j = 0; j < 4; j++)
                wmma::store_matrix_sync(&stg[(wr * 32 + i * 16) * LDS_F + wc * 64 + j * 16],
                                        acc[i][j], LDS_F, wmma::mem_row_major);
        __syncthreads();

        const float* srow = &stg[r * LDS_F + cb];

        if (l < NL - 1) {
            #pragma unroll
            for (int j0 = 0; j0 < 64; j0 += 8) {
                u32 hi[4], lo[4];
                #pragma unroll
                for (int jj = 0; jj < 8; jj += 2) {
                    int c = cb + j0 + jj;
                    float z0 = leaky(srow[j0 + jj] + cstb[c]);
                    float z1 = leaky(srow[j0 + jj + 1] + cstb[c + 1]);
                    __nv_bfloat16 h0 = __float2bfloat16(z0), h1 = __float2bfloat16(z1);
                    hi[jj >> 1] = bfpack(h0, h1);
                    lo[jj >> 1] = bfpack(__float2bfloat16(z0 - __bfloat162float(h0)),
                                         __float2bfloat16(z1 - __bfloat162float(h1)));
                }
                *(uint4*)&Ah[r * LDA + cb + j0] = make_uint4(hi[0], hi[1], hi[2], hi[3]);
                *(uint4*)&Al[r * LDA + cb + j0] = make_uint4(lo[0], lo[1], lo[2], lo[3]);
            }
        } else if (EPI == 0 || EPI == 1) {
            float s = 0.f, q = 0.f;
            #pragma unroll
            for (int j = 0; j < 64; j++) {
                float z = srow[j] + cstb[cb + j];
                s += z; q += z * z;
            }
            s += __shfl_xor_sync(0xffffffffu, s, 1);
            q += __shfl_xor_sync(0xffffffffu, q, 1);
            float m = s * (1.f / (float)D);
            float var = q * (1.f / (float)D) - m * m;
            float inv = rsqrtf(var + EPSf);
            int sidx = (EPI == 1 && valid) ? esrc[grow] : 0;
            #pragma unroll
            for (int j0 = 0; j0 < 64; j0 += 4) {
                float o[4];
                #pragma unroll
                for (int jj = 0; jj < 4; jj++) {
                    int c = cb + j0 + jj;
                    float z = srow[j0 + jj] + cstb[c];
                    o[jj] = (z - m) * inv * cstg[c] + cstl[c];
                }
                if (EPI == 1) {
                    if (valid)
                        red4(&g_acc[(size_t)sidx * D + cb + j0], o[0], o[1], o[2], o[3]);
                } else if (valid) {
                    *(float4*)&out[(size_t)grow * D + cb + j0] = make_float4(o[0], o[1], o[2], o[3]);
                }
            }
        } else {
            // conv: write g_h only (self-term/dis^2 handled in gather)
            #pragma unroll
            for (int j0 = 0; j0 < 64; j0 += 4) {
                float4 v = *(const float4*)&srow[j0];
                if (valid)
                    *(float4*)&g_h[(size_t)grow * D + cb + j0] = v;
            }
        }
        __syncthreads();
    }
}

// ---------------- host orchestration ----------------
extern "C" void kernel_launch(void* const* d_in, const int* in_sizes, int n_in,
                              void* d_out, int out_size)
{
    const float* node_feat = (const float*)d_in[0];
    const float* edge_feat = (const float*)d_in[1];
    const int*   ei        = (const int*)d_in[2];
    const float* enW1 = (const float*)d_in[3];  const float* enb1 = (const float*)d_in[4];
    const float* enW2 = (const float*)d_in[5];  const float* enb2 = (const float*)d_in[6];
    const float* enW3 = (const float*)d_in[7];  const float* enb3 = (const float*)d_in[8];
    const float* enlg = (const float*)d_in[9];  const float* enlb = (const float*)d_in[10];
    const float* eeW1 = (const float*)d_in[11]; const float* eeb1 = (const float*)d_in[12];
    const float* eeW2 = (const float*)d_in[13]; const float* eeb2 = (const float*)d_in[14];
    const float* eeW3 = (const float*)d_in[15]; const float* eeb3 = (const float*)d_in[16];
    const float* eelg = (const float*)d_in[17]; const float* eelb = (const float*)d_in[18];
    const float* procW = (const float*)d_in[19];
    const float* procb = (const float*)d_in[20];
    const float* bng   = (const float*)d_in[21];
    const float* bnb   = (const float*)d_in[22];
    const float* dW1 = (const float*)d_in[23]; const float* db1 = (const float*)d_in[24];
    const float* dW2 = (const float*)d_in[25]; const float* db2 = (const float*)d_in[26];
    const float* dW3 = (const float*)d_in[27]; const float* db3 = (const float*)d_in[28];
    const float* dlg = (const float*)d_in[29]; const float* dlb = (const float*)d_in[30];
    float* out = (float*)d_out;

    float* hn_ptr = nullptr; cudaGetSymbolAddress((void**)&hn_ptr, g_hn);
    float* y_ptr = nullptr;  cudaGetSymbolAddress((void**)&y_ptr, g_y);

    cudaFuncSetAttribute(k_fused<NODE_IN, 2, 0, false>, cudaFuncAttributeMaxDynamicSharedMemorySize, SMEM_F);
    cudaFuncSetAttribute(k_fused<EDGE_IN, 2, 1, false>, cudaFuncAttributeMaxDynamicSharedMemorySize, SMEM_F);
    cudaFuncSetAttribute(k_fused<0, 1, 2, false>, cudaFuncAttributeMaxDynamicSharedMemorySize, SMEM_F);
    cudaFuncSetAttribute(k_fused<0, 1, 2, true>,  cudaFuncAttributeMaxDynamicSharedMemorySize, SMEM_F);
    cudaFuncSetAttribute(k_fused<0, 3, 0, false>, cudaFuncAttributeMaxDynamicSharedMemorySize, SMEM_F);

    int NnT = (Nn + 127) / 128, EeT = Ee / 128;

    // 1: weight splits   2: zero   3: count
    k_wsplit_all<<<dim3(64, NSLOT), 256>>>(enW2, enW3, eeW2, eeW3, procW, dW1, dW2, dW3);
    k_zero<<<512, 256>>>();
    k_count<<<(Ee + 255) / 256, 256>>>(ei);
    // 4: edge encoder (profiled launch) — scatter-sum into g_acc
    k_fused<EDGE_IN, 2, 1, false><<<EeT, 256, SMEM_F>>>(
        edge_feat, 2, 3, 0, eeb2, eeb3, nullptr, eeW1, eeb1, eelg, eelb,
        nullptr, ei, Ee);
    // 5: node encoder
    k_fused<NODE_IN, 2, 0, false><<<NnT, 256, SMEM_F>>>(
        node_feat, 0, 1, 0, enb2, enb3, nullptr, enW1, enb1, enlg, enlb,
        hn_ptr, nullptr, Nn);
    // CSR build + mix
    k_scan<<<1, 1024>>>();
    k_dis<<<(Nn + 255) / 256, 256>>>();
    k_fill<<<(Ee + 255) / 256, 256>>>(ei);
    k_mix<<<(Nn * D + 255) / 256, 256>>>();

    // processor steps
    for (int s = 0; s < STEPS; s++) {
        const float* b0 = procb + (size_t)(s * 2 + 0) * D;
        const float* b1 = procb + (size_t)(s * 2 + 1) * D;

        k_fused<0, 1, 2, false><<<NnT, 256, SMEM_F>>>(
            hn_ptr, 4 + 2 * s, 0, 0, nullptr, nullptr, nullptr,
            nullptr, nullptr, nullptr, nullptr, nullptr, nullptr, Nn);
        k_bnzero<<<1, 128>>>();
        k_gatherA<<<512, 256>>>(b0);
        k_bnfin<<<1, 128>>>(bng + (size_t)s * D, bnb + (size_t)s * D);

        k_fused<0, 1, 2, true><<<NnT, 256, SMEM_F>>>(
            y_ptr, 5 + 2 * s, 0, 0, nullptr, nullptr, nullptr,
            nullptr, nullptr, nullptr, nullptr, nullptr, nullptr, Nn);
        k_gatherB<<<512, 256>>>(b1);
    }

    // decoder (fused 3 layers + LN)
    k_fused<0, 3, 0, false><<<NnT, 256, SMEM_F>>>(
        hn_ptr, 14, 15, 16, db1, db2, db3,
        nullptr, nullptr, dlg, dlb, out, nullptr, Nn);
}

// round 7
// speedup vs baseline: 2.7428x; 1.3685x over previous
#include <cuda_runtime.h>
#include <cuda_bf16.h>
#include <cstddef>
#include <cstdint>

#define Nn 50000
#define Ee 800000
#define D 128
#define NODE_IN 19
#define EDGE_IN 4
#define STEPS 5
#define EPSf 1e-5f

typedef unsigned long long u64;
typedef unsigned int u32;

// ---------------- device scratch ----------------
__device__ float g_hn[Nn * D];
__device__ float g_acc[Nn * D];
__device__ float g_h[Nn * D];
__device__ float g_y[Nn * D];
__device__ float g_cnt[Nn];
__device__ float g_dis[Nn];
__device__ int   g_degi[Nn];
__device__ int   g_fill[Nn];
__device__ int   g_rowoff[Nn + 1];
__device__ int   g_csrs[Ee];
__device__ float g_csrw[Ee];
__device__ float g_bnsum[D];
__device__ float g_bnsq[D];
__device__ float g_bnscale[D];
__device__ float g_bnshift[D];

#define NSLOT 17
__device__ __nv_bfloat16 g_whi[NSLOT * D * D];
__device__ __nv_bfloat16 g_wlo[NSLOT * D * D];

__device__ __forceinline__ float leaky(float v) { return v > 0.f ? v : 0.05f * v; }

__device__ __forceinline__ void red4(float* p, float a, float b, float c, float d) {
    asm volatile("red.global.add.v4.f32 [%0], {%1,%2,%3,%4};"
                 :: "l"(p), "f"(a), "f"(b), "f"(c), "f"(d) : "memory");
}
__device__ __forceinline__ void red2(float* p, float a, float b) {
    asm volatile("red.global.add.v2.f32 [%0], {%1,%2};"
                 :: "l"(p), "f"(a), "f"(b) : "memory");
}
__device__ __forceinline__ u32 bfpack(__nv_bfloat16 a, __nv_bfloat16 b) {
    __nv_bfloat162 t = __halves2bfloat162(a, b);
    return *(u32*)&t;
}
__device__ __forceinline__ u32 smem_u32(const void* p) {
    u32 a; asm("{ .reg .u64 t; cvta.to.shared.u64 t, %1; cvt.u32.u64 %0, t; }"
               : "=r"(a) : "l"(p));
    return a;
}
__device__ __forceinline__ void ldsm4(u32 addr, u32& r0, u32& r1, u32& r2, u32& r3) {
    asm volatile("ldmatrix.sync.aligned.m8n8.x4.shared.b16 {%0,%1,%2,%3}, [%4];"
                 : "=r"(r0), "=r"(r1), "=r"(r2), "=r"(r3) : "r"(addr));
}
__device__ __forceinline__ void mma16816(float* c, const u32* a, const u32* b) {
    asm volatile("mma.sync.aligned.m16n8k16.row.col.f32.bf16.bf16.f32 "
                 "{%0,%1,%2,%3}, {%4,%5,%6,%7}, {%8,%9}, {%0,%1,%2,%3};"
                 : "+f"(c[0]), "+f"(c[1]), "+f"(c[2]), "+f"(c[3])
                 : "r"(a[0]), "r"(a[1]), "r"(a[2]), "r"(a[3]), "r"(b[0]), "r"(b[1]));
}

// ---------------- utility kernels ----------------
__global__ void k_zero() {
    int i = blockIdx.x * blockDim.x + threadIdx.x;
    int stride = gridDim.x * blockDim.x;
    for (int j = i; j < Nn * D; j += stride) g_acc[j] = 0.f;
    for (int j = i; j < Nn; j += stride) {
        g_cnt[j] = 0.f; g_degi[j] = 0; g_fill[j] = 0;
    }
}

__global__ void k_count(const int* __restrict__ ei) {
    int e = blockIdx.x * blockDim.x + threadIdx.x;
    if (e >= Ee) return;
    atomicAdd(&g_cnt[ei[e]], 1.f);
    atomicAdd(&g_degi[ei[Ee + e]], 1);
}

__global__ void k_scan() {
    __shared__ int ts[1024];
    int t = threadIdx.x;
    const int CH = (Nn + 1023) / 1024;
    int start = t * CH;
    int end = min(start + CH, Nn);
    int sum = 0;
    for (int i = start; i < end; i++) sum += g_degi[i];
    ts[t] = sum;
    __syncthreads();
    for (int off = 1; off < 1024; off <<= 1) {
        int v = (t >= off) ? ts[t - off] : 0;
        __syncthreads();
        ts[t] += v;
        __syncthreads();
    }
    int run = (t == 0) ? 0 : ts[t - 1];
    for (int i = start; i < end; i++) { g_rowoff[i] = run; run += g_degi[i]; }
    if (t == 1023) g_rowoff[Nn] = run;
}

__global__ void k_dis() {
    int i = blockIdx.x * blockDim.x + threadIdx.x;
    if (i < Nn) g_dis[i] = rsqrtf((float)g_degi[i] + 1.0f);
}

__global__ void k_fill(const int* __restrict__ ei) {
    int e = blockIdx.x * blockDim.x + threadIdx.x;
    if (e >= Ee) return;
    int s = ei[e], d = ei[Ee + e];
    int pos = g_rowoff[d] + atomicAdd(&g_fill[d], 1);
    g_csrs[pos] = s;
    g_csrw[pos] = g_dis[s] * g_dis[d];
}

__global__ void k_mix() {
    int i = blockIdx.x * blockDim.x + threadIdx.x;
    if (i < Nn * D) g_hn[i] += g_acc[i] / fmaxf(g_cnt[i >> 7], 1.f);
}

__global__ void k_bnzero() {
    int c = threadIdx.x;
    if (c < D) { g_bnsum[c] = 0.f; g_bnsq[c] = 0.f; }
}

__global__ void k_bnfin(const float* __restrict__ g, const float* __restrict__ b) {
    int c = threadIdx.x;
    if (c < D) {
        float m = g_bnsum[c] * (1.f / (float)Nn);
        float v = g_bnsq[c] * (1.f / (float)Nn) - m * m;
        float sc = g[c] * rsqrtf(v + EPSf);
        g_bnscale[c] = sc;
        g_bnshift[c] = b[c] - m * sc;
    }
}

// ---------------- CSR gather kernels (warp per node) ----------------
__global__ void __launch_bounds__(256) k_gatherA(const float* __restrict__ b0) {
    int lane = threadIdx.x & 31;
    int gw = blockIdx.x * 8 + (threadIdx.x >> 5);
    int nw = gridDim.x * 8;
    int c0 = lane * 4;
    float4 bb = *(const float4*)&b0[c0];
    float s0 = 0.f, s1 = 0.f, s2 = 0.f, s3 = 0.f;
    float q0 = 0.f, q1 = 0.f, q2 = 0.f, q3 = 0.f;

    for (int node = gw; node < Nn; node += nw) {
        float dd = g_dis[node];
        float d2 = dd * dd;
        float4 a = *(const float4*)&g_h[(size_t)node * D + c0];
        a.x *= d2; a.y *= d2; a.z *= d2; a.w *= d2;
        int p = g_rowoff[node], p1 = g_rowoff[node + 1];
        for (; p + 1 < p1; p += 2) {
            int sA = g_csrs[p];     float wA = g_csrw[p];
            int sB = g_csrs[p + 1]; float wB = g_csrw[p + 1];
            float4 vA = *(const float4*)&g_h[(size_t)sA * D + c0];
            float4 vB = *(const float4*)&g_h[(size_t)sB * D + c0];
            a.x = fmaf(vA.x, wA, a.x); a.y = fmaf(vA.y, wA, a.y);
            a.z = fmaf(vA.z, wA, a.z); a.w = fmaf(vA.w, wA, a.w);
            a.x = fmaf(vB.x, wB, a.x); a.y = fmaf(vB.y, wB, a.y);
            a.z = fmaf(vB.z, wB, a.z); a.w = fmaf(vB.w, wB, a.w);
        }
        if (p < p1) {
            int sA = g_csrs[p]; float wA = g_csrw[p];
            float4 vA = *(const float4*)&g_h[(size_t)sA * D + c0];
            a.x = fmaf(vA.x, wA, a.x); a.y = fmaf(vA.y, wA, a.y);
            a.z = fmaf(vA.z, wA, a.z); a.w = fmaf(vA.w, wA, a.w);
        }
        float v0 = leaky(a.x + bb.x), v1 = leaky(a.y + bb.y);
        float v2 = leaky(a.z + bb.z), v3 = leaky(a.w + bb.w);
        *(float4*)&g_y[(size_t)node * D + c0] = make_float4(v0, v1, v2, v3);
        s0 += v0; s1 += v1; s2 += v2; s3 += v3;
        q0 += v0 * v0; q1 += v1 * v1; q2 += v2 * v2; q3 += v3 * v3;
    }
    red4(&g_bnsum[c0], s0, s1, s2, s3);
    red4(&g_bnsq[c0],  q0, q1, q2, q3);
}

__global__ void __launch_bounds__(256) k_gatherB(const float* __restrict__ b1) {
    int lane = threadIdx.x & 31;
    int gw = blockIdx.x * 8 + (threadIdx.x >> 5);
    int nw = gridDim.x * 8;
    int c0 = lane * 4;
    float4 bb = *(const float4*)&b1[c0];

    for (int node = gw; node < Nn; node += nw) {
        float dd = g_dis[node];
        float d2 = dd * dd;
        float4 a = *(const float4*)&g_h[(size_t)node * D + c0];
        a.x *= d2; a.y *= d2; a.z *= d2; a.w *= d2;
        int p = g_rowoff[node], p1 = g_rowoff[node + 1];
        for (; p + 1 < p1; p += 2) {
            int sA = g_csrs[p];     float wA = g_csrw[p];
            int sB = g_csrs[p + 1]; float wB = g_csrw[p + 1];
            float4 vA = *(const float4*)&g_h[(size_t)sA * D + c0];
            float4 vB = *(const float4*)&g_h[(size_t)sB * D + c0];
            a.x = fmaf(vA.x, wA, a.x); a.y = fmaf(vA.y, wA, a.y);
            a.z = fmaf(vA.z, wA, a.z); a.w = fmaf(vA.w, wA, a.w);
            a.x = fmaf(vB.x, wB, a.x); a.y = fmaf(vB.y, wB, a.y);
            a.z = fmaf(vB.z, wB, a.z); a.w = fmaf(vB.w, wB, a.w);
        }
        if (p < p1) {
            int sA = g_csrs[p]; float wA = g_csrw[p];
            float4 vA = *(const float4*)&g_h[(size_t)sA * D + c0];
            a.x = fmaf(vA.x, wA, a.x); a.y = fmaf(vA.y, wA, a.y);
            a.z = fmaf(vA.z, wA, a.z); a.w = fmaf(vA.w, wA, a.w);
        }
        float4 h4 = *(const float4*)&g_hn[(size_t)node * D + c0];
        h4.x += a.x + bb.x; h4.y += a.y + bb.y;
        h4.z += a.z + bb.z; h4.w += a.w + bb.w;
        *(float4*)&g_hn[(size_t)node * D + c0] = h4;
    }
}

// all 17 weight splits: grid (64, 17)
__global__ void k_wsplit_all(
    const float* __restrict__ enW2, const float* __restrict__ enW3,
    const float* __restrict__ eeW2, const float* __restrict__ eeW3,
    const float* __restrict__ procW,
    const float* __restrict__ dW1, const float* __restrict__ dW2,
    const float* __restrict__ dW3)
{
    int slot = blockIdx.y;
    const float* W;
    if (slot == 0) W = enW2;
    else if (slot == 1) W = enW3;
    else if (slot == 2) W = eeW2;
    else if (slot == 3) W = eeW3;
    else if (slot < 14) W = procW + (size_t)(slot - 4) * D * D;
    else if (slot == 14) W = dW1;
    else if (slot == 15) W = dW2;
    else W = dW3;
    int i = blockIdx.x * 256 + threadIdx.x;
    int k = i >> 7, n = i & 127;
    float v = W[i];
    __nv_bfloat16 h = __float2bfloat16(v);
    g_whi[slot * D * D + n * D + k] = h;
    g_wlo[slot * D * D + n * D + k] = __float2bfloat16(v - __bfloat162float(h));
}

// ---------------- persistent fused MLP kernel (raw mma) ----------------
// A/W smem tiles: 128 rows x 128 bf16, row stride 136 elems (272 B). hi/lo pairs.
// EPI: 0 = LN -> out; 1 = LN -> red2 scatter g_acc[esrc]; 2 = conv (g_h only)
template <int KIN, int NL, int EPI, bool BN>
__global__ void __launch_bounds__(256, 1) k_fused(
    const float* __restrict__ in,
    int slot0, int slot1, int slot2,
    const float* __restrict__ wb0, const float* __restrict__ wb1, const float* __restrict__ wb2,
    const float* __restrict__ W1, const float* __restrict__ bias1,
    const float* __restrict__ lng, const float* __restrict__ lnb,
    float* __restrict__ out, const int* __restrict__ esrc, int M, int nT)
{
    constexpr bool PRE = (NL <= 2);
    constexpr int NW = PRE ? NL : 1;
    constexpr int OFF_AL = 34816;
    constexpr int OFF_W = 69632;
    constexpr int OFF_W1S = OFF_W + NW * 69632;
    constexpr int OFF_C = OFF_W1S + (KIN > 0 ? KIN * 512 : 0);
    extern __shared__ char smem[];
    u32 sb = smem_u32(smem);

    int tid = threadIdx.x, lane = tid & 31, wid = tid >> 5;
    int wr = wid & 3, wc = wid >> 2, gid = lane >> 2, tig = lane & 3;

    float* sbias0 = (float*)(smem + OFF_C);
    float* sbias1 = (float*)(smem + OFF_C + 512);
    float* sbias2 = (float*)(smem + OFF_C + 1024);
    float* sg  = (float*)(smem + OFF_C + 1536);
    float* sl  = (float*)(smem + OFF_C + 2048);
    float* sb1 = (float*)(smem + OFF_C + 2560);
    float* rs  = (float*)(smem + OFF_C + 3072);   // [128][2]
    float* rq  = (float*)(smem + OFF_C + 4096);   // [128][2]
    float* sbias[3] = {sbias0, sbias1, sbias2};

    int slots[3] = {slot0, slot1, slot2};
    const float* wbs[3] = {wb0, wb1, wb2};

    if (tid < 128) {
        if (EPI != 2) {
            #pragma unroll
            for (int l = 0; l < NL; l++) sbias[l][tid] = wbs[l][tid];
            sg[tid] = lng[tid]; sl[tid] = lnb[tid];
        }
        if (KIN > 0) sb1[tid] = bias1[tid];
    }
    if (KIN > 0) {
        float* W1s = (float*)(smem + OFF_W1S);
        for (int i = tid; i < KIN * 128; i += 256) W1s[i] = W1[i];
    }
    if (PRE) {
        #pragma unroll
        for (int l = 0; l < NL; l++) {
            const uint4* ph = ((const uint4*)g_whi) + (size_t)slots[l] * 2048;
            const uint4* pl = ((const uint4*)g_wlo) + (size_t)slots[l] * 2048;
            char* dh = smem + OFF_W + l * 69632;
            for (int i = tid; i < 2048; i += 256) {
                int row = i >> 4, c = i & 15;
                *(uint4*)(dh + row * 272 + c * 16) = ph[row * 16 + c];
                *(uint4*)(dh + 34816 + row * 272 + c * 16) = pl[row * 16 + c];
            }
        }
    }
    __syncthreads();

    // ldmatrix per-lane byte offsets
    u32 a_lo = (u32)((((lane & 7) + ((lane >> 3) & 1) * 8) * 136 + (lane >> 4) * 8) * 2);
    u32 b_lo = (u32)((((lane & 7) + ((lane >> 4) & 1) * 8) * 136 + ((lane >> 3) & 1) * 8) * 2);

    for (int t = blockIdx.x; t < nT; t += gridDim.x) {
        int tb = t * 128;

        // ---- build A tile (bf16 hi/lo) ----
        if (KIN > 0) {
            float* W1s = (float*)(smem + OFF_W1S);
            int r = tid >> 1, half = tid & 1;
            int gr = min(tb + r, M - 1);
            float xv[KIN > 0 ? KIN : 1];
            #pragma unroll
            for (int k = 0; k < KIN; k++) xv[k] = in[(size_t)gr * KIN + k];
            #pragma unroll
            for (int c4 = 0; c4 < 4; c4++) {
                int cbase = half * 64 + c4 * 16;
                float a16[16];
                #pragma unroll
                for (int j = 0; j < 16; j++) a16[j] = sb1[cbase + j];
                #pragma unroll
                for (int k = 0; k < KIN; k++) {
                    float x = xv[k];
                    const float* wrow = &W1s[k * 128 + cbase];
                    #pragma unroll
                    for (int j = 0; j < 16; j++) a16[j] = fmaf(x, wrow[j], a16[j]);
                }
                #pragma unroll
                for (int j = 0; j < 16; j += 2) {
                    float z0 = leaky(a16[j]), z1 = leaky(a16[j + 1]);
                    __nv_bfloat16 h0 = __float2bfloat16(z0), h1 = __float2bfloat16(z1);
                    *(u32*)(smem + (size_t)(r * 136 + cbase + j) * 2) = bfpack(h0, h1);
                    *(u32*)(smem + OFF_AL + (size_t)(r * 136 + cbase + j) * 2) =
                        bfpack(__float2bfloat16(z0 - __bfloat162float(h0)),
                               __float2bfloat16(z1 - __bfloat162float(h1)));
                }
            }
        } else {
            for (int idx = tid; idx < 4096; idx += 256) {
                int row = idx >> 5, c4 = idx & 31;
                int gr = min(tb + row, M - 1);
                float4 v = ((const float4*)in)[(size_t)gr * 32 + c4];
                if (BN) {
                    int c = c4 * 4;
                    v.x = fmaf(v.x, g_bnscale[c],     g_bnshift[c]);
                    v.y = fmaf(v.y, g_bnscale[c + 1], g_bnshift[c + 1]);
                    v.z = fmaf(v.z, g_bnscale[c + 2], g_bnshift[c + 2]);
                    v.w = fmaf(v.w, g_bnscale[c + 3], g_bnshift[c + 3]);
                }
                __nv_bfloat16 h0 = __float2bfloat16(v.x), h1 = __float2bfloat16(v.y);
                __nv_bfloat16 h2 = __float2bfloat16(v.z), h3 = __float2bfloat16(v.w);
                u32 hi01 = bfpack(h0, h1), hi23 = bfpack(h2, h3);
                u32 lo01 = bfpack(__float2bfloat16(v.x - __bfloat162float(h0)),
                                  __float2bfloat16(v.y - __bfloat162float(h1)));
                u32 lo23 = bfpack(__float2bfloat16(v.z - __bfloat162float(h2)),
                                  __float2bfloat16(v.w - __bfloat162float(h3)));
                *(uint2*)(smem + (size_t)(row * 136 + c4 * 4) * 2) = make_uint2(hi01, hi23);
                *(uint2*)(smem + OFF_AL + (size_t)(row * 136 + c4 * 4) * 2) = make_uint2(lo01, lo23);
            }
        }
        __syncthreads();

        // ---- layers ----
        #pragma unroll
        for (int l = 0; l < NL; l++) {
            u32 wbase;
            if (PRE) {
                wbase = sb + OFF_W + l * 69632;
            } else {
                const uint4* ph = ((const uint4*)g_whi) + (size_t)slots[l] * 2048;
                const uint4* pl = ((const uint4*)g_wlo) + (size_t)slots[l] * 2048;
                for (int i = tid; i < 2048; i += 256) {
                    int row = i >> 4, c = i & 15;
                    *(uint4*)(smem + OFF_W + row * 272 + c * 16) = ph[row * 16 + c];
                    *(uint4*)(smem + OFF_W + 34816 + row * 272 + c * 16) = pl[row * 16 + c];
                }
                __syncthreads();
                wbase = sb + OFF_W;
            }

            float acc[2][8][4];
            #pragma unroll
            for (int i = 0; i < 2; i++)
                #pragma unroll
                for (int j = 0; j < 8; j++)
                    #pragma unroll
                    for (int k = 0; k < 4; k++) acc[i][j][k] = 0.f;

            u32 ab_hi = sb + (u32)(wr * 32 * 272) + a_lo;
            u32 ab_lo = ab_hi + OFF_AL;
            u32 bb_hi = wbase + (u32)(wc * 64 * 272) + b_lo;
            u32 bb_lo = bb_hi + 34816;

            #pragma unroll
            for (int ks = 0; ks < 8; ks++) {
                u32 ah[2][4], alo[2][4];
                #pragma unroll
                for (int rt = 0; rt < 2; rt++) {
                    ldsm4(ab_hi + rt * (16 * 272) + ks * 32,
                          ah[rt][0], ah[rt][1], ah[rt][2], ah[rt][3]);
                    ldsm4(ab_lo + rt * (16 * 272) + ks * 32,
                          alo[rt][0], alo[rt][1], alo[rt][2], alo[rt][3]);
                }
                u32 bh[8][2], bl[8][2];
                #pragma unroll
                for (int np = 0; np < 4; np++) {
                    u32 r0, r1, r2, r3;
                    ldsm4(bb_hi + np * (16 * 272) + ks * 32, r0, r1, r2, r3);
                    bh[np * 2][0] = r0; bh[np * 2][1] = r1;
                    bh[np * 2 + 1][0] = r2; bh[np * 2 + 1][1] = r3;
                    ldsm4(bb_lo + np * (16 * 272) + ks * 32, r0, r1, r2, r3);
                    bl[np * 2][0] = r0; bl[np * 2][1] = r1;
                    bl[np * 2 + 1][0] = r2; bl[np * 2 + 1][1] = r3;
                }
                #pragma unroll
                for (int rt = 0; rt < 2; rt++)
                    #pragma unroll
                    for (int nt = 0; nt < 8; nt++) {
                        mma16816(acc[rt][nt], ah[rt], bh[nt]);
                        mma16816(acc[rt][nt], ah[rt], bl[nt]);
                        mma16816(acc[rt][nt], alo[rt], bh[nt]);
                    }
            }
            __syncthreads();   // all A/W reads done

            if (l < NL - 1) {
                const float* bias = sbias[l];
                #pragma unroll
                for (int rt = 0; rt < 2; rt++) {
                    int r0 = wr * 32 + rt * 16 + gid;
                    #pragma unroll
                    for (int nt = 0; nt < 8; nt++) {
                        int c = wc * 64 + nt * 8 + tig * 2;
                        float b0v = bias[c], b1v = bias[c + 1];
                        float z0 = leaky(acc[rt][nt][0] + b0v);
                        float z1 = leaky(acc[rt][nt][1] + b1v);
                        float z2 = leaky(acc[rt][nt][2] + b0v);
                        float z3 = leaky(acc[rt][nt][3] + b1v);
                        __nv_bfloat16 h0 = __float2bfloat16(z0), h1 = __float2bfloat16(z1);
                        __nv_bfloat16 h2 = __float2bfloat16(z2), h3 = __float2bfloat16(z3);
                        *(u32*)(smem + (size_t)(r0 * 136 + c) * 2) = bfpack(h0, h1);
                        *(u32*)(smem + OFF_AL + (size_t)(r0 * 136 + c) * 2) =
                            bfpack(__float2bfloat16(z0 - __bfloat162float(h0)),
                                   __float2bfloat16(z1 - __bfloat162float(h1)));
                        *(u32*)(smem + (size_t)((r0 + 8) * 136 + c) * 2) = bfpack(h2, h3);
                        *(u32*)(smem + OFF_AL + (size_t)((r0 + 8) * 136 + c) * 2) =
                            bfpack(__float2bfloat16(z2 - __bfloat162float(h2)),
                                   __float2bfloat16(z3 - __bfloat162float(h3)));
                    }
                }
                __syncthreads();
            } else if (EPI == 2) {
                #pragma unroll
                for (int rt = 0; rt < 2; rt++) {
                    int r0 = wr * 32 + rt * 16 + gid;
                    int gr0 = tb + r0, gr1 = gr0 + 8;
                    #pragma unroll
                    for (int nt = 0; nt < 8; nt++) {
                        int c = wc * 64 + nt * 8 + tig * 2;
                        if (gr0 < M)
                            *(float2*)&g_h[(size_t)gr0 * D + c] =
                                make_float2(acc[rt][nt][0], acc[rt][nt][1]);
                        if (gr1 < M)
                            *(float2*)&g_h[(size_t)gr1 * D + c] =
                                make_float2(acc[rt][nt][2], acc[rt][nt][3]);
                    }
                }
                __syncthreads();
            } else {
                const float* bias = sbias[NL - 1];
                #pragma unroll
                for (int rt = 0; rt < 2; rt++) {
                    float s0 = 0.f, q0 = 0.f, s1 = 0.f, q1 = 0.f;
                    #pragma unroll
                    for (int nt = 0; nt < 8; nt++) {
                        int c = wc * 64 + nt * 8 + tig * 2;
                        float b0v = bias[c], b1v = bias[c + 1];
                        float z0 = acc[rt][nt][0] + b0v, z1 = acc[rt][nt][1] + b1v;
                        float z2 = acc[rt][nt][2] + b0v, z3 = acc[rt][nt][3] + b1v;
                        s0 += z0 + z1; q0 += z0 * z0 + z1 * z1;
                        s1 += z2 + z3; q1 += z2 * z2 + z3 * z3;
                    }
                    s0 += __shfl_xor_sync(0xffffffffu, s0, 1);
                    q0 += __shfl_xor_sync(0xffffffffu, q0, 1);
                    s1 += __shfl_xor_sync(0xffffffffu, s1, 1);
                    q1 += __shfl_xor_sync(0xffffffffu, q1, 1);
                    s0 += __shfl_xor_sync(0xffffffffu, s0, 2);
                    q0 += __shfl_xor_sync(0xffffffffu, q0, 2);
                    s1 += __shfl_xor_sync(0xffffffffu, s1, 2);
                    q1 += __shfl_xor_sync(0xffffffffu, q1, 2);
                    int r0 = wr * 32 + rt * 16 + gid;
                    if (tig == 0) {
                        rs[r0 * 2 + wc] = s0; rq[r0 * 2 + wc] = q0;
                        rs[(r0 + 8) * 2 + wc] = s1; rq[(r0 + 8) * 2 + wc] = q1;
                    }
                }
                __syncthreads();
                #pragma unroll
                for (int rt = 0; rt < 2; rt++) {
                    int r0 = wr * 32 + rt * 16 + gid;
                    float S0 = rs[r0 * 2] + rs[r0 * 2 + 1];
                    float Q0 = rq[r0 * 2] + rq[r0 * 2 + 1];
                    float S1 = rs[(r0 + 8) * 2] + rs[(r0 + 8) * 2 + 1];
                    float Q1 = rq[(r0 + 8) * 2] + rq[(r0 + 8) * 2 + 1];
                    float m0 = S0 * (1.f / (float)D);
                    float i0 = rsqrtf(Q0 * (1.f / (float)D) - m0 * m0 + EPSf);
                    float m1 = S1 * (1.f / (float)D);
                    float i1 = rsqrtf(Q1 * (1.f / (float)D) - m1 * m1 + EPSf);
                    int gr0 = tb + r0, gr1 = gr0 + 8;
                    int sidx0 = 0, sidx1 = 0;
                    if (EPI == 1) {
                        if (gr0 < M) sidx0 = esrc[gr0];
                        if (gr1 < M) sidx1 = esrc[gr1];
                    }
                    #pragma unroll
                    for (int nt = 0; nt < 8; nt++) {
                        int c = wc * 64 + nt * 8 + tig * 2;
                        float b0v = bias[c], b1v = bias[c + 1];
                        float g0 = sg[c], g1 = sg[c + 1];
                        float l0 = sl[c], l1 = sl[c + 1];
                        float o0 = (acc[rt][nt][0] + b0v - m0) * i0 * g0 + l0;
                        float o1 = (acc[rt][nt][1] + b1v - m0) * i0 * g1 + l1;
                        float o2 = (acc[rt][nt][2] + b0v - m1) * i1 * g0 + l0;
                        float o3 = (acc[rt][nt][3] + b1v - m1) * i1 * g1 + l1;
                        if (EPI == 0) {
                            if (gr0 < M) *(float2*)&out[(size_t)gr0 * D + c] = make_float2(o0, o1);
                            if (gr1 < M) *(float2*)&out[(size_t)gr1 * D + c] = make_float2(o2, o3);
                        } else {
                            if (gr0 < M) red2(&g_acc[(size_t)sidx0 * D + c], o0, o1);
                            if (gr1 < M) red2(&g_acc[(size_t)sidx1 * D + c], o2, o3);
                        }
                    }
                }
                __syncthreads();
            }
        }
    }
}

// ---------------- host orchestration ----------------
extern "C" void kernel_launch(void* const* d_in, const int* in_sizes, int n_in,
                              void* d_out, int out_size)
{
    const float* node_feat = (const float*)d_in[0];
    const float* edge_feat = (const float*)d_in[1];
    const int*   ei        = (const int*)d_in[2];
    const float* enW1 = (const float*)d_in[3];  const float* enb1 = (const float*)d_in[4];
    const float* enW2 = (const float*)d_in[5];  const float* enb2 = (const float*)d_in[6];
    const float* enW3 = (const float*)d_in[7];  const float* enb3 = (const float*)d_in[8];
    const float* enlg = (const float*)d_in[9];  const float* enlb = (const float*)d_in[10];
    const float* eeW1 = (const float*)d_in[11]; const float* eeb1 = (const float*)d_in[12];
    const float* eeW2 = (const float*)d_in[13]; const float* eeb2 = (const float*)d_in[14];
    const float* eeW3 = (const float*)d_in[15]; const float* eeb3 = (const float*)d_in[16];
    const float* procW = (const float*)d_in[19];
    const float* procb = (const float*)d_in[20];
    const float* bng   = (const float*)d_in[21];
    const float* bnb   = (const float*)d_in[22];
    const float* dW1 = (const float*)d_in[23]; const float* db1 = (const float*)d_in[24];
    const float* dW2 = (const float*)d_in[25]; const float* db2 = (const float*)d_in[26];
    const float* dW3 = (const float*)d_in[27]; const float* db3 = (const float*)d_in[28];
    const float* dlg = (const float*)d_in[29]; const float* dlb = (const float*)d_in[30];
    const float* eelg = (const float*)d_in[17]; const float* eelb = (const float*)d_in[18];
    float* out = (float*)d_out;

    float* hn_ptr = nullptr; cudaGetSymbolAddress((void**)&hn_ptr, g_hn);
    float* y_ptr = nullptr;  cudaGetSymbolAddress((void**)&y_ptr, g_y);

    const int SM_EDGE = 69632 + 2 * 69632 + EDGE_IN * 512 + 5120;   // 216064
    const int SM_NODE = 69632 + 2 * 69632 + NODE_IN * 512 + 5120;   // 223744
    const int SM_CONV = 69632 + 1 * 69632 + 5120;                    // 144384
    const int SM_DEC  = 69632 + 1 * 69632 + 5120;                    // 144384

    cudaFuncSetAttribute(k_fused<EDGE_IN, 2, 1, false>, cudaFuncAttributeMaxDynamicSharedMemorySize, SM_EDGE);
    cudaFuncSetAttribute(k_fused<NODE_IN, 2, 0, false>, cudaFuncAttributeMaxDynamicSharedMemorySize, SM_NODE);
    cudaFuncSetAttribute(k_fused<0, 1, 2, false>, cudaFuncAttributeMaxDynamicSharedMemorySize, SM_CONV);
    cudaFuncSetAttribute(k_fused<0, 1, 2, true>,  cudaFuncAttributeMaxDynamicSharedMemorySize, SM_CONV);
    cudaFuncSetAttribute(k_fused<0, 3, 0, false>, cudaFuncAttributeMaxDynamicSharedMemorySize, SM_DEC);

    int NnT = (Nn + 127) / 128, EeT = Ee / 128;
    int G = 148;

    // 1: weight splits   2: zero   3: count
    k_wsplit_all<<<dim3(64, NSLOT), 256>>>(enW2, enW3, eeW2, eeW3, procW, dW1, dW2, dW3);
    k_zero<<<512, 256>>>();
    k_count<<<(Ee + 255) / 256, 256>>>(ei);
    // 4: edge encoder (profiled) — LN + scatter-sum into g_acc
    k_fused<EDGE_IN, 2, 1, false><<<G, 256, SM_EDGE>>>(
        edge_feat, 2, 3, 0, eeb2, eeb3, nullptr, eeW1, eeb1, eelg, eelb,
        nullptr, ei, Ee, EeT);
    // 5: node encoder
    k_fused<NODE_IN, 2, 0, false><<<G, 256, SM_NODE>>>(
        node_feat, 0, 1, 0, enb2, enb3, nullptr, enW1, enb1, enlg, enlb,
        hn_ptr, nullptr, Nn, NnT);
    // CSR build + mix
    k_scan<<<1, 1024>>>();
    k_dis<<<(Nn + 255) / 256, 256>>>();
    k_fill<<<(Ee + 255) / 256, 256>>>(ei);
    k_mix<<<(Nn * D + 255) / 256, 256>>>();

    // processor steps
    for (int s = 0; s < STEPS; s++) {
        const float* b0 = procb + (size_t)(s * 2 + 0) * D;
        const float* b1 = procb + (size_t)(s * 2 + 1) * D;

        k_fused<0, 1, 2, false><<<G, 256, SM_CONV>>>(
            hn_ptr, 4 + 2 * s, 0, 0, nullptr, nullptr, nullptr,
            nullptr, nullptr, nullptr, nullptr, nullptr, nullptr, Nn, NnT);
        k_bnzero<<<1, 128>>>();
        k_gatherA<<<512, 256>>>(b0);
        k_bnfin<<<1, 128>>>(bng + (size_t)s * D, bnb + (size_t)s * D);

        k_fused<0, 1, 2, true><<<G, 256, SM_CONV>>>(
            y_ptr, 5 + 2 * s, 0, 0, nullptr, nullptr, nullptr,
            nullptr, nullptr, nullptr, nullptr, nullptr, nullptr, Nn, NnT);
        k_gatherB<<<512, 256>>>(b1);
    }

    // decoder (3 layers + LN, per-layer W reload)
    k_fused<0, 3, 0, false><<<G, 256, SM_DEC>>>(
        hn_ptr, 14, 15, 16, db1, db2, db3,
        nullptr, nullptr, dlg, dlb, out, nullptr, Nn, NnT);
}